// round 10
// baseline (speedup 1.0000x reference)
#include <cuda_runtime.h>
#include <math.h>
#include <stdint.h>

#define B 32
#define C 128
#define L 4096
#define NROW (B*C)
#define BCL (B*C*L)            // 16777216
#define FL 9
#define DIM 512
#define NYL ((size_t)BCL)

// ---------------- scratch (device globals; no allocation) ----------------
__device__ float g_a1[BCL];
__device__ float g_a2[BCL];
__device__ float g_a3[BCL];
__device__ float g_attn[B*(C/4)*L];
__device__ float g_feat[3*B*C];          // per-level feature means
__device__ float g_h1[B*DIM];
__device__ float g_h2[B*2*DIM];
__device__ float g_wt[3*C*4*C];          // Winograd gates weights [lvl][ci][m][co]
__device__ float g_w2t[2*32*C];          // attn2 weights [lvl][ci][co]

__device__ __forceinline__ float gelu_f(float x){
    return 0.5f*x*(1.0f+erff(x*0.7071067811865476f));
}
__device__ __forceinline__ float sigmoid_f(float x){
    return 1.0f/(1.0f+expf(-x));
}

// ---- packed f32x2 helpers (Blackwell FFMA2) ----
__device__ __forceinline__ unsigned long long pack2(float lo, float hi){
    unsigned long long r;
    asm("mov.b64 %0, {%1, %2};" : "=l"(r) : "f"(lo), "f"(hi));
    return r;
}
__device__ __forceinline__ unsigned long long fma2(unsigned long long a, unsigned long long b, unsigned long long c){
    unsigned long long d;
    asm("fma.rn.f32x2 %0, %1, %2, %3;" : "=l"(d) : "l"(a), "l"(b), "l"(c));
    return d;
}
__device__ __forceinline__ unsigned long long add2(unsigned long long a, unsigned long long b){
    unsigned long long d;
    asm("add.rn.f32x2 %0, %1, %2;" : "=l"(d) : "l"(a), "l"(b));
    return d;
}
__device__ __forceinline__ float2 unpack2(unsigned long long v){
    float2 f;
    asm("mov.b64 {%0, %1}, %2;" : "=f"(f.x), "=f"(f.y) : "l"(v));
    return f;
}

// ---------------- mean over L (level 0 only) ----------------
__global__ __launch_bounds__(256) void mean_kernel(const float* __restrict__ x,
                                                   float* __restrict__ feat){
    int row = blockIdx.x;
    const float4* p = (const float4*)(x + (size_t)row*L);
    float s = 0.f;
    for (int i = threadIdx.x; i < L/4; i += 256){
        float4 v = p[i];
        s += (v.x+v.y)+(v.z+v.w);
    }
    __shared__ float red[256];
    red[threadIdx.x] = s; __syncthreads();
    for (int off = 128; off > 0; off >>= 1){
        if (threadIdx.x < off) red[threadIdx.x] += red[threadIdx.x+off];
        __syncthreads();
    }
    if (threadIdx.x == 0) feat[row] = red[0] * (1.0f/(float)L);
}

// ---------------- MLP layers (warp-per-output GEMV) ----------------
__global__ __launch_bounds__(256) void mlp_l1(const float* __restrict__ feat,
                                              const float* __restrict__ sw, const float* __restrict__ sb,
                                              float* __restrict__ h1){
    int b = blockIdx.y;
    int j = blockIdx.x*8 + (threadIdx.x >> 5);
    int lane = threadIdx.x & 31;
    float4 w = ((const float4*)(sw + (size_t)j*C))[lane];
    float4 f = ((const float4*)(feat + b*C))[lane];
    float s = w.x*f.x + w.y*f.y + w.z*f.z + w.w*f.w;
    #pragma unroll
    for (int off = 16; off > 0; off >>= 1) s += __shfl_xor_sync(0xffffffffu, s, off);
    if (lane == 0) h1[b*DIM + j] = gelu_f(s + sb[j]);
}

__global__ __launch_bounds__(256) void mlp_l2(const float* __restrict__ h1,
                                              const float* __restrict__ w1, const float* __restrict__ b1,
                                              float* __restrict__ h2){
    __shared__ __align__(16) float sh[DIM];
    int b = blockIdx.y, t = threadIdx.x;
    for (int i = t; i < DIM/4; i += 256)
        ((float4*)sh)[i] = ((const float4*)(h1 + b*DIM))[i];
    __syncthreads();
    int j = blockIdx.x*8 + (t >> 5);
    int lane = t & 31;
    const float4* wr = (const float4*)(w1 + (size_t)j*DIM);
    float s = 0.f;
    #pragma unroll
    for (int i = 0; i < 4; i++){
        float4 w = wr[i*32 + lane];
        float4 f = ((const float4*)sh)[i*32 + lane];
        s += w.x*f.x + w.y*f.y + w.z*f.z + w.w*f.w;
    }
    #pragma unroll
    for (int off = 16; off > 0; off >>= 1) s += __shfl_xor_sync(0xffffffffu, s, off);
    if (lane == 0) h2[b*2*DIM + j] = gelu_f(s + b1[j]);
}

__global__ __launch_bounds__(576) void mlp_l3(const float* __restrict__ h2,
                                              const float* __restrict__ w2, const float* __restrict__ b2,
                                              float* __restrict__ lo, float* __restrict__ hi){
    __shared__ __align__(16) float sh[2*DIM];
    int b = blockIdx.x, t = threadIdx.x;
    for (int i = t; i < 2*DIM/4; i += 576)
        ((float4*)sh)[i] = ((const float4*)(h2 + b*2*DIM))[i];
    __syncthreads();
    int j = t >> 5, lane = t & 31;     // 18 warps
    const float4* wr = (const float4*)(w2 + (size_t)j*2*DIM);
    float s = 0.f;
    #pragma unroll
    for (int i = 0; i < 8; i++){
        float4 w = wr[i*32 + lane];
        float4 f = ((const float4*)sh)[i*32 + lane];
        s += w.x*f.x + w.y*f.y + w.z*f.z + w.w*f.w;
    }
    #pragma unroll
    for (int off = 16; off > 0; off >>= 1) s += __shfl_xor_sync(0xffffffffu, s, off);
    if (lane == 0){
        float v = s + b2[j];
        if (j < FL) lo[b*FL + j] = v;
        else        hi[b*FL + (j-FL)] = v;
    }
}

// ---------------- ortho loss (last level only) + energy=0 ----------------
__global__ void ortho_kernel(const float* __restrict__ lo, float* __restrict__ out_scalars){
    int b = threadIdx.x;
    float v[FL]; float ss = 0.f;
    #pragma unroll
    for (int k = 0; k < FL; k++){ v[k] = lo[b*FL+k]; ss += v[k]*v[k]; }
    float den = sqrtf(ss) + 1e-8f;
    float S = 0.f, sq = 0.f;
    #pragma unroll
    for (int k = 0; k < FL; k++){
        float n = v[k]/den;
        S  += fabsf(n);
        sq += n*n;
    }
    float S2  = S*S;
    float amp = fabsf(sq - 1.0f);
    float sm  = fabsf(v[0]);
    #pragma unroll
    for (int k = 1; k < FL; k++) sm += fabsf(v[k]-v[k-1]);
    sm += fabsf(v[FL-1]);
    #pragma unroll
    for (int off = 16; off > 0; off >>= 1){
        S2  += __shfl_xor_sync(0xffffffffu, S2,  off);
        amp += __shfl_xor_sync(0xffffffffu, amp, off);
        sm  += __shfl_xor_sync(0xffffffffu, sm,  off);
    }
    if (b == 0){
        float shift  = 3.0f * S2 / (32.0f*81.0f);
        float ampm   = amp / 32.0f;
        float smm    = sm / (32.0f*10.0f);
        out_scalars[0] = 0.01f*(shift + ampm) + 0.1f*smm;
        out_scalars[1] = 0.0f;
    }
}

// ---------------- per-sample depthwise 9-tap (edge pad) + mean accumulate ----------------
#define DTL 1024
__global__ __launch_bounds__(256) void dw_kernel(
    const float* __restrict__ x, const float* __restrict__ lo, const float* __restrict__ hi,
    float* __restrict__ out_a, float* __restrict__ out_d, float* __restrict__ feat_next)
{
    int row = blockIdx.y;
    int b   = row >> 7;
    int l0  = blockIdx.x * DTL;
    __shared__ __align__(16) float s[DTL + 16];
    __shared__ float wsum[8];
    const float* xr = x + (size_t)row * L;
    int t = threadIdx.x, lane = t & 31, wid = t >> 5;
    {
        const float4* xv = (const float4*)(xr + l0);
        ((float4*)(s + 4))[t] = xv[t];
    }
    if (t < 4){
        int li = l0 - 4 + t;
        s[t] = xr[max(li, 0)];
        int ri = l0 + DTL + t;
        s[DTL + 4 + t] = xr[min(ri, L-1)];
    }
    unsigned long long pf[FL];
    #pragma unroll
    for (int k = 0; k < FL; k++) pf[k] = pack2(__ldg(&lo[b*FL+k]), __ldg(&hi[b*FL+k]));
    __syncthreads();

    int i0 = t * 4;
    float win[12];
    #pragma unroll
    for (int j = 0; j < 12; j++) win[j] = s[i0 + j];
    unsigned long long acc[4];
    #pragma unroll
    for (int p = 0; p < 4; p++) acc[p] = 0ull;
    #pragma unroll
    for (int k = 0; k < FL; k++){
        #pragma unroll
        for (int p = 0; p < 4; p++){
            unsigned long long vv = pack2(win[p+k], win[p+k]);
            acc[p] = fma2(vv, pf[k], acc[p]);
        }
    }
    float4 ra, rd;
    float2 f0 = unpack2(acc[0]), f1 = unpack2(acc[1]), f2 = unpack2(acc[2]), f3 = unpack2(acc[3]);
    ra.x = f0.x; ra.y = f1.x; ra.z = f2.x; ra.w = f3.x;
    rd.x = f0.y; rd.y = f1.y; rd.z = f2.y; rd.w = f3.y;
    size_t idx = (size_t)row*L + l0 + i0;
    *(float4*)(out_a + idx) = ra;
    *(float4*)(out_d + idx) = rd;

    if (feat_next){
        float s4 = (ra.x + ra.y) + (ra.z + ra.w);
        #pragma unroll
        for (int off = 16; off > 0; off >>= 1) s4 += __shfl_xor_sync(0xffffffffu, s4, off);
        if (lane == 0) wsum[wid] = s4;
        __syncthreads();
        if (t == 0){
            float tot = 0.f;
            #pragma unroll
            for (int w = 0; w < 8; w++) tot += wsum[w];
            atomicAdd(feat_next + row, tot * (1.0f/(float)L));
        }
    }
}

// ---------------- weight prep: Winograd F(2,3) transform ----------------
// U0=g0, U1=(g0+g1+g2)/2, U2=(g0-g1+g2)/2, U3=g2; layout [lvl][ci][m][co]
__global__ void wino_w_kernel(const float* __restrict__ gw, float* __restrict__ wt){
    int idx = blockIdx.x*256 + threadIdx.x;
    if (idx < 3*C*4*C){
        int lvl = idx / (C*4*C);
        int r   = idx % (C*4*C);
        int ci  = r / (4*C);
        int m   = (r / C) & 3;
        int co  = r % C;
        const float* g = gw + (((size_t)lvl*C + co)*C + ci)*3;
        float g0 = g[0], g1 = g[1], g2 = g[2];
        float u;
        if      (m == 0) u = g0;
        else if (m == 1) u = 0.5f*(g0+g1+g2);
        else if (m == 2) u = 0.5f*(g0-g1+g2);
        else             u = g2;
        wt[idx] = u;
    }
}
__global__ void prep2_kernel(const float* __restrict__ attn2_w, float* __restrict__ w2t,
                             float* __restrict__ feat){
    int idx = blockIdx.x*256 + threadIdx.x;
    if (idx < 2*32*C){
        int lvl = idx / (32*C);
        int r   = idx % (32*C);
        int ci  = r >> 7, co = r & 127;
        w2t[idx] = attn2_w[((size_t)lvl*C + co)*32 + ci];
    }
    if (idx < 2*B*C) feat[B*C + idx] = 0.f;   // zero feat levels 1,2
}

// ---------------- fused gates: Winograd conv3 + optional attn2 + optional attn1 ----------------
// phase1 (ATTN): det' = det*(1+sig(W2*a+b2)) -> yh
// phase2: z1 = winograd_conv3(cur)+bias; out = cur + sig(z1)*det'
// phase3 (A1): a_out = gelu(W1*out + b1)
#define P_X 68
#define SO_U  (C*P_X*4)                 // 34816: union (s_w chunks / s_w2 / s_w1)
#define GSM_PLAIN (SO_U + 8*4*C*4)      // 51200
#define SO_A  GSM_PLAIN                 // 51200
#define GSM_ATTN  (SO_A + 32*64*4)      // 59392

template<bool ATTN, bool A1>
__global__ __launch_bounds__(256, 2) void gatesf_kernel(
    const float* __restrict__ cur, const float* __restrict__ det_raw,
    const float* __restrict__ wt, const float* __restrict__ bias,
    const float* __restrict__ a_in, const float* __restrict__ w2t, const float* __restrict__ bias2,
    float* __restrict__ yh_out, float* __restrict__ out,
    const float* __restrict__ w1, const float* __restrict__ b1, float* __restrict__ a_out)
{
    extern __shared__ __align__(16) char smem[];
    float* s_x  = (float*)smem;              // [128][68], j=0 <-> l0-1
    float* s_w  = (float*)(smem + SO_U);     // phase2 chunks [8ci][4m][128co]
    float* s_w2 = (float*)(smem + SO_U);     // phase1 [32][128]
    float* s_a  = (float*)(smem + SO_A);     // [32][64]
    int l0 = blockIdx.x*64, b = blockIdx.y, t = threadIdx.x;
    int wid = t >> 5, lane = t & 31, co0 = wid*16, lq = lane*2;

    for (int idx = t; idx < C*66; idx += 256){
        int ci = idx/66, j = idx%66;
        int li = l0 + j - 1;
        float v = 0.f;
        if (li >= 0 && li < L) v = cur[((size_t)(b*C+ci))*L + li];
        s_x[ci*P_X + j] = v;
    }
    if (ATTN){
        for (int idx = t; idx < 32*64; idx += 256){
            int ci = idx >> 6, j = idx & 63;
            s_a[idx] = a_in[((size_t)(b*32+ci))*L + l0 + j];
        }
        for (int idx = t; idx < 32*C; idx += 256) s_w2[idx] = w2t[idx];
    }
    __syncthreads();

    // ---- phase 1 (ATTN): det' -> yh_out ----
    if (ATTN){
        unsigned long long acc2[8][2];
        #pragma unroll
        for (int c = 0; c < 8; c++){ acc2[c][0] = 0ull; acc2[c][1] = 0ull; }
        #pragma unroll 4
        for (int ci = 0; ci < 32; ci++){
            float2 xv = *(const float2*)(&s_a[ci*64 + lq]);
            unsigned long long p0 = pack2(xv.x, xv.x);
            unsigned long long p1 = pack2(xv.y, xv.y);
            const ulonglong2* wp = (const ulonglong2*)(&s_w2[ci*C + co0]);
            unsigned long long wr[8];
            ((ulonglong2*)wr)[0] = wp[0];
            ((ulonglong2*)wr)[1] = wp[1];
            ((ulonglong2*)wr)[2] = wp[2];
            ((ulonglong2*)wr)[3] = wp[3];
            #pragma unroll
            for (int c = 0; c < 8; c++){
                acc2[c][0] = fma2(wr[c], p0, acc2[c][0]);
                acc2[c][1] = fma2(wr[c], p1, acc2[c][1]);
            }
        }
        #pragma unroll
        for (int c = 0; c < 8; c++){
            int co = co0 + 2*c;
            float2 z0 = unpack2(acc2[c][0]);   // l=lq,   (co,co+1)
            float2 z1 = unpack2(acc2[c][1]);   // l=lq+1
            #pragma unroll
            for (int s = 0; s < 2; s++){
                float bv = __ldg(&bias2[co+s]);
                size_t idx = ((size_t)(b*C+co+s))*L + l0 + lq;
                float2 dv = *(const float2*)(det_raw + idx);
                dv.x *= 1.0f + sigmoid_f((s ? z0.y : z0.x) + bv);
                dv.y *= 1.0f + sigmoid_f((s ? z1.y : z1.x) + bv);
                *(float2*)(yh_out + idx) = dv;
            }
        }
    }

    // ---- phase 2: Winograd F(2,3) conv ----
    unsigned long long acc[8][4];
    #pragma unroll
    for (int c = 0; c < 8; c++)
        #pragma unroll
        for (int m = 0; m < 4; m++) acc[c][m] = 0ull;

    for (int ci0 = 0; ci0 < C; ci0 += 8){
        __syncthreads();
        for (int idx = t; idx < 8*4*C; idx += 256) s_w[idx] = wt[ci0*4*C + idx];
        __syncthreads();
        #pragma unroll
        for (int ci = 0; ci < 8; ci++){
            const float* xr = &s_x[(ci0+ci)*P_X + lq];
            float2 v01 = *(const float2*)xr;
            float2 v23 = *(const float2*)(xr + 2);
            float D0 = v01.x - v23.x;
            float D1 = v01.y + v23.x;
            float D2 = v23.x - v01.y;
            float D3 = v01.y - v23.y;
            unsigned long long p[4];
            p[0] = pack2(D0, D0);
            p[1] = pack2(D1, D1);
            p[2] = pack2(D2, D2);
            p[3] = pack2(D3, D3);
            #pragma unroll
            for (int m = 0; m < 4; m++){
                const ulonglong2* wp = (const ulonglong2*)(&s_w[(ci*4+m)*C + co0]);
                unsigned long long wr[8];
                ((ulonglong2*)wr)[0] = wp[0];
                ((ulonglong2*)wr)[1] = wp[1];
                ((ulonglong2*)wr)[2] = wp[2];
                ((ulonglong2*)wr)[3] = wp[3];
                #pragma unroll
                for (int c = 0; c < 8; c++)
                    acc[c][m] = fma2(wr[c], p[m], acc[c][m]);
            }
        }
    }

    // ---- epilogue: inverse transform + gate + write ----
    const unsigned long long neg1 = pack2(-1.0f, -1.0f);
    float2 oreg[8][2];
    #pragma unroll
    for (int c = 0; c < 8; c++){
        int co = co0 + 2*c;
        unsigned long long y0 = add2(add2(acc[c][0], acc[c][1]), acc[c][2]);
        unsigned long long y1 = fma2(neg1, acc[c][3], fma2(neg1, acc[c][2], acc[c][1]));
        float2 z0 = unpack2(y0);   // l=lq
        float2 z1 = unpack2(y1);   // l=lq+1
        #pragma unroll
        for (int s = 0; s < 2; s++){
            int cs = co + s;
            float bv = __ldg(&bias[cs]);
            size_t idx = ((size_t)(b*C+cs))*L + l0 + lq;
            const float* dsrc = ATTN ? yh_out : det_raw;
            float2 dv = *(const float2*)(dsrc + idx);
            float c0 = s_x[cs*P_X + lq + 1];
            float c1 = s_x[cs*P_X + lq + 2];
            float2 ov;
            ov.x = c0 + sigmoid_f((s ? z0.y : z0.x) + bv)*dv.x;
            ov.y = c1 + sigmoid_f((s ? z1.y : z1.x) + bv)*dv.y;
            *(float2*)(out + idx) = ov;
            if (A1) oreg[c][s] = ov;
        }
    }

    // ---- phase 3 (A1): attn1 = gelu(W1*out + b1) ----
    if (A1){
        __syncthreads();                       // all cur reads done
        #pragma unroll
        for (int c = 0; c < 8; c++){
            int co = co0 + 2*c;
            #pragma unroll
            for (int s = 0; s < 2; s++){
                s_x[(co+s)*P_X + lq + 1] = oreg[c][s].x;
                s_x[(co+s)*P_X + lq + 2] = oreg[c][s].y;
            }
        }
        float* s_w1 = s_w;
        for (int idx = t; idx < 32*C; idx += 256){
            int ci = idx >> 5, c2 = idx & 31;
            s_w1[idx] = w1[c2*C + ci];
        }
        __syncthreads();
        int c2b = wid*4;
        unsigned long long acc3[2][2];
        acc3[0][0] = 0ull; acc3[0][1] = 0ull; acc3[1][0] = 0ull; acc3[1][1] = 0ull;
        #pragma unroll 8
        for (int ci = 0; ci < C; ci++){
            float x0 = s_x[ci*P_X + lq + 1];
            float x1 = s_x[ci*P_X + lq + 2];
            unsigned long long p0 = pack2(x0, x0);
            unsigned long long p1 = pack2(x1, x1);
            ulonglong2 wv = *(const ulonglong2*)(&s_w1[ci*32 + c2b]);
            acc3[0][0] = fma2(wv.x, p0, acc3[0][0]);
            acc3[0][1] = fma2(wv.x, p1, acc3[0][1]);
            acc3[1][0] = fma2(wv.y, p0, acc3[1][0]);
            acc3[1][1] = fma2(wv.y, p1, acc3[1][1]);
        }
        #pragma unroll
        for (int pc = 0; pc < 2; pc++){
            int c2 = c2b + 2*pc;
            float2 z0 = unpack2(acc3[pc][0]);
            float2 z1 = unpack2(acc3[pc][1]);
            #pragma unroll
            for (int s = 0; s < 2; s++){
                float bv = __ldg(&b1[c2+s]);
                size_t idx = ((size_t)(b*32 + c2 + s))*L + l0 + lq;
                float2 av;
                av.x = gelu_f((s ? z0.y : z0.x) + bv);
                av.y = gelu_f((s ? z1.y : z1.x) + bv);
                *(float2*)(a_out + idx) = av;
            }
        }
    }
}

// ---------------- host launch ----------------
extern "C" void kernel_launch(void* const* d_in, const int* in_sizes, int n_in,
                              void* d_out, int out_size)
{
    const float* x       = (const float*)d_in[0];
    const float* stat_w  = (const float*)d_in[1];
    const float* stat_b  = (const float*)d_in[2];
    const float* wg1_w   = (const float*)d_in[3];
    const float* wg1_b   = (const float*)d_in[4];
    const float* wg2_w   = (const float*)d_in[5];
    const float* wg2_b   = (const float*)d_in[6];
    const float* gates_w = (const float*)d_in[7];
    const float* gates_b = (const float*)d_in[8];
    const float* attn1_w = (const float*)d_in[9];
    const float* attn1_b = (const float*)d_in[10];
    const float* attn2_w = (const float*)d_in[11];
    const float* attn2_b = (const float*)d_in[12];
    float* out = (float*)d_out;

    float *a1, *a2, *a3, *attn, *feat, *h1, *h2, *wt, *w2t;
    cudaGetSymbolAddress((void**)&a1,   g_a1);
    cudaGetSymbolAddress((void**)&a2,   g_a2);
    cudaGetSymbolAddress((void**)&a3,   g_a3);
    cudaGetSymbolAddress((void**)&attn, g_attn);
    cudaGetSymbolAddress((void**)&feat, g_feat);
    cudaGetSymbolAddress((void**)&h1,   g_h1);
    cudaGetSymbolAddress((void**)&h2,   g_h2);
    cudaGetSymbolAddress((void**)&wt,   g_wt);
    cudaGetSymbolAddress((void**)&w2t,  g_w2t);

    float* yl  = out;
    float* yh0 = out + NYL;
    float* yh1 = out + 2*NYL;
    float* yh2 = out + 3*NYL;
    float* scal= out + 4*NYL;
    float* lo_all = out + 4*NYL + 2;
    float* hi_all = lo_all + 3*B*FL;

    cudaFuncSetAttribute((const void*)gatesf_kernel<false,true>,  cudaFuncAttributeMaxDynamicSharedMemorySize, GSM_PLAIN);
    cudaFuncSetAttribute((const void*)gatesf_kernel<true,true>,   cudaFuncAttributeMaxDynamicSharedMemorySize, GSM_ATTN);
    cudaFuncSetAttribute((const void*)gatesf_kernel<true,false>,  cudaFuncAttributeMaxDynamicSharedMemorySize, GSM_ATTN);

    wino_w_kernel<<<(3*C*4*C + 255)/256, 256>>>(gates_w, wt);
    prep2_kernel<<<(2*32*C + 255)/256, 256>>>(attn2_w, w2t, feat);

    const float* ain[3]  = {x, a1, a2};
    float*       aout[3] = {a1, a2, a3};
    float*       dets[3] = {yh0, yh1, yh2};

    mean_kernel<<<NROW, 256>>>(x, feat);
    for (int lvl = 0; lvl < 3; lvl++){
        float* lo = lo_all + lvl*B*FL;
        float* hi = hi_all + lvl*B*FL;
        const float* f = feat + lvl*B*C;
        mlp_l1<<<dim3(DIM/8, B), 256>>>(f, stat_w, stat_b, h1);
        mlp_l2<<<dim3(2*DIM/8, B), 256>>>(h1, wg1_w, wg1_b, h2);
        mlp_l3<<<B, 576>>>(h2, wg2_w, wg2_b, lo, hi);
        float* fnext = (lvl < 2) ? (feat + (lvl+1)*B*C) : nullptr;
        dw_kernel<<<dim3(L/DTL, NROW), 256>>>(ain[lvl], lo, hi, aout[lvl], dets[lvl], fnext);
    }

    ortho_kernel<<<1, 32>>>(lo_all + 2*B*FL, scal);

    // i = 2: gates (no attn2) + fused attn1 for level 1
    gatesf_kernel<false,true><<<dim3(L/64, B), 256, GSM_PLAIN>>>(
        a3, yh2, wt + 2*C*4*C, gates_b + 2*C,
        nullptr, nullptr, nullptr, nullptr, a1,
        attn1_w + 1*(C/4)*C, attn1_b + (C/4), attn);
    // i = 1: gates + attn2(level 1) + fused attn1 for level 0
    gatesf_kernel<true,true><<<dim3(L/64, B), 256, GSM_ATTN>>>(
        a1, yh1, wt + 1*C*4*C, gates_b + 1*C,
        attn, w2t + 32*C, attn2_b + C, yh1, a2,
        attn1_w, attn1_b, attn);
    // i = 0: gates + attn2(level 0)
    gatesf_kernel<true,false><<<dim3(L/64, B), 256, GSM_ATTN>>>(
        a2, yh0, wt, gates_b,
        attn, w2t, attn2_b, yh0, yl,
        nullptr, nullptr, nullptr);
}

// round 12
// speedup vs baseline: 1.3402x; 1.3402x over previous
#include <cuda_runtime.h>
#include <math.h>
#include <stdint.h>

#define B 32
#define C 128
#define L 4096
#define NROW (B*C)
#define BCL (B*C*L)            // 16777216
#define FL 9
#define DIM 512
#define NYL ((size_t)BCL)

// ---------------- scratch (device globals; no allocation) ----------------
__device__ float g_a1[BCL];
__device__ float g_a2[BCL];
__device__ float g_a3[BCL];
__device__ float g_attn[B*(C/4)*L];
__device__ float g_feat[3*B*C];          // per-level feature means
__device__ float g_h1[B*DIM];
__device__ float g_h2[B*2*DIM];
__device__ float g_wt[3*C*3*C];          // gates weights [lvl][ci][k][co]
__device__ float g_w2t[2*32*C];          // attn2 weights [lvl][ci][co]

__device__ __forceinline__ float gelu_f(float x){
    return 0.5f*x*(1.0f+erff(x*0.7071067811865476f));
}
__device__ __forceinline__ float sigmoid_f(float x){
    return 1.0f/(1.0f+expf(-x));
}

// ---- packed f32x2 helpers (Blackwell FFMA2) ----
__device__ __forceinline__ unsigned long long pack2(float lo, float hi){
    unsigned long long r;
    asm("mov.b64 %0, {%1, %2};" : "=l"(r) : "f"(lo), "f"(hi));
    return r;
}
__device__ __forceinline__ unsigned long long fma2(unsigned long long a, unsigned long long b, unsigned long long c){
    unsigned long long d;
    asm("fma.rn.f32x2 %0, %1, %2, %3;" : "=l"(d) : "l"(a), "l"(b), "l"(c));
    return d;
}
__device__ __forceinline__ float2 unpack2(unsigned long long v){
    float2 f;
    asm("mov.b64 {%0, %1}, %2;" : "=f"(f.x), "=f"(f.y) : "l"(v));
    return f;
}

// ---------------- mean over L (level 0 only) ----------------
__global__ __launch_bounds__(256) void mean_kernel(const float* __restrict__ x,
                                                   float* __restrict__ feat){
    int row = blockIdx.x;
    const float4* p = (const float4*)(x + (size_t)row*L);
    float s = 0.f;
    for (int i = threadIdx.x; i < L/4; i += 256){
        float4 v = p[i];
        s += (v.x+v.y)+(v.z+v.w);
    }
    __shared__ float red[256];
    red[threadIdx.x] = s; __syncthreads();
    for (int off = 128; off > 0; off >>= 1){
        if (threadIdx.x < off) red[threadIdx.x] += red[threadIdx.x+off];
        __syncthreads();
    }
    if (threadIdx.x == 0) feat[row] = red[0] * (1.0f/(float)L);
}

// ---------------- MLP layers (warp-per-output GEMV) ----------------
__global__ __launch_bounds__(256) void mlp_l1(const float* __restrict__ feat,
                                              const float* __restrict__ sw, const float* __restrict__ sb,
                                              float* __restrict__ h1){
    int b = blockIdx.y;
    int j = blockIdx.x*8 + (threadIdx.x >> 5);
    int lane = threadIdx.x & 31;
    float4 w = ((const float4*)(sw + (size_t)j*C))[lane];
    float4 f = ((const float4*)(feat + b*C))[lane];
    float s = w.x*f.x + w.y*f.y + w.z*f.z + w.w*f.w;
    #pragma unroll
    for (int off = 16; off > 0; off >>= 1) s += __shfl_xor_sync(0xffffffffu, s, off);
    if (lane == 0) h1[b*DIM + j] = gelu_f(s + sb[j]);
}

__global__ __launch_bounds__(256) void mlp_l2(const float* __restrict__ h1,
                                              const float* __restrict__ w1, const float* __restrict__ b1,
                                              float* __restrict__ h2){
    __shared__ __align__(16) float sh[DIM];
    int b = blockIdx.y, t = threadIdx.x;
    for (int i = t; i < DIM/4; i += 256)
        ((float4*)sh)[i] = ((const float4*)(h1 + b*DIM))[i];
    __syncthreads();
    int j = blockIdx.x*8 + (t >> 5);
    int lane = t & 31;
    const float4* wr = (const float4*)(w1 + (size_t)j*DIM);
    float s = 0.f;
    #pragma unroll
    for (int i = 0; i < 4; i++){
        float4 w = wr[i*32 + lane];
        float4 f = ((const float4*)sh)[i*32 + lane];
        s += w.x*f.x + w.y*f.y + w.z*f.z + w.w*f.w;
    }
    #pragma unroll
    for (int off = 16; off > 0; off >>= 1) s += __shfl_xor_sync(0xffffffffu, s, off);
    if (lane == 0) h2[b*2*DIM + j] = gelu_f(s + b1[j]);
}

__global__ __launch_bounds__(576) void mlp_l3(const float* __restrict__ h2,
                                              const float* __restrict__ w2, const float* __restrict__ b2,
                                              float* __restrict__ lo, float* __restrict__ hi){
    __shared__ __align__(16) float sh[2*DIM];
    int b = blockIdx.x, t = threadIdx.x;
    for (int i = t; i < 2*DIM/4; i += 576)
        ((float4*)sh)[i] = ((const float4*)(h2 + b*2*DIM))[i];
    __syncthreads();
    int j = t >> 5, lane = t & 31;     // 18 warps
    const float4* wr = (const float4*)(w2 + (size_t)j*2*DIM);
    float s = 0.f;
    #pragma unroll
    for (int i = 0; i < 8; i++){
        float4 w = wr[i*32 + lane];
        float4 f = ((const float4*)sh)[i*32 + lane];
        s += w.x*f.x + w.y*f.y + w.z*f.z + w.w*f.w;
    }
    #pragma unroll
    for (int off = 16; off > 0; off >>= 1) s += __shfl_xor_sync(0xffffffffu, s, off);
    if (lane == 0){
        float v = s + b2[j];
        if (j < FL) lo[b*FL + j] = v;
        else        hi[b*FL + (j-FL)] = v;
    }
}

// ---------------- ortho loss (last level only) + energy=0 ----------------
__global__ void ortho_kernel(const float* __restrict__ lo, float* __restrict__ out_scalars){
    int b = threadIdx.x;
    float v[FL]; float ss = 0.f;
    #pragma unroll
    for (int k = 0; k < FL; k++){ v[k] = lo[b*FL+k]; ss += v[k]*v[k]; }
    float den = sqrtf(ss) + 1e-8f;
    float S = 0.f, sq = 0.f;
    #pragma unroll
    for (int k = 0; k < FL; k++){
        float n = v[k]/den;
        S  += fabsf(n);
        sq += n*n;
    }
    float S2  = S*S;
    float amp = fabsf(sq - 1.0f);
    float sm  = fabsf(v[0]);
    #pragma unroll
    for (int k = 1; k < FL; k++) sm += fabsf(v[k]-v[k-1]);
    sm += fabsf(v[FL-1]);
    #pragma unroll
    for (int off = 16; off > 0; off >>= 1){
        S2  += __shfl_xor_sync(0xffffffffu, S2,  off);
        amp += __shfl_xor_sync(0xffffffffu, amp, off);
        sm  += __shfl_xor_sync(0xffffffffu, sm,  off);
    }
    if (b == 0){
        float shift  = 3.0f * S2 / (32.0f*81.0f);
        float ampm   = amp / 32.0f;
        float smm    = sm / (32.0f*10.0f);
        out_scalars[0] = 0.01f*(shift + ampm) + 0.1f*smm;
        out_scalars[1] = 0.0f;
    }
}

// ---------------- per-sample depthwise 9-tap (edge pad) + mean accumulate ----------------
#define DTL 1024
__global__ __launch_bounds__(256) void dw_kernel(
    const float* __restrict__ x, const float* __restrict__ lo, const float* __restrict__ hi,
    float* __restrict__ out_a, float* __restrict__ out_d, float* __restrict__ feat_next)
{
    int row = blockIdx.y;
    int b   = row >> 7;
    int l0  = blockIdx.x * DTL;
    __shared__ __align__(16) float s[DTL + 16];
    __shared__ float wsum[8];
    const float* xr = x + (size_t)row * L;
    int t = threadIdx.x, lane = t & 31, wid = t >> 5;
    {
        const float4* xv = (const float4*)(xr + l0);
        ((float4*)(s + 4))[t] = xv[t];
    }
    if (t < 4){
        int li = l0 - 4 + t;
        s[t] = xr[max(li, 0)];
        int ri = l0 + DTL + t;
        s[DTL + 4 + t] = xr[min(ri, L-1)];
    }
    unsigned long long pf[FL];
    #pragma unroll
    for (int k = 0; k < FL; k++) pf[k] = pack2(__ldg(&lo[b*FL+k]), __ldg(&hi[b*FL+k]));
    __syncthreads();

    int i0 = t * 4;
    float win[12];
    #pragma unroll
    for (int j = 0; j < 12; j++) win[j] = s[i0 + j];
    unsigned long long acc[4];
    #pragma unroll
    for (int p = 0; p < 4; p++) acc[p] = 0ull;
    #pragma unroll
    for (int k = 0; k < FL; k++){
        #pragma unroll
        for (int p = 0; p < 4; p++){
            unsigned long long vv = pack2(win[p+k], win[p+k]);
            acc[p] = fma2(vv, pf[k], acc[p]);
        }
    }
    float4 ra, rd;
    float2 f0 = unpack2(acc[0]), f1 = unpack2(acc[1]), f2 = unpack2(acc[2]), f3 = unpack2(acc[3]);
    ra.x = f0.x; ra.y = f1.x; ra.z = f2.x; ra.w = f3.x;
    rd.x = f0.y; rd.y = f1.y; rd.z = f2.y; rd.w = f3.y;
    size_t idx = (size_t)row*L + l0 + i0;
    *(float4*)(out_a + idx) = ra;
    *(float4*)(out_d + idx) = rd;

    if (feat_next){
        float s4 = (ra.x + ra.y) + (ra.z + ra.w);
        #pragma unroll
        for (int off = 16; off > 0; off >>= 1) s4 += __shfl_xor_sync(0xffffffffu, s4, off);
        if (lane == 0) wsum[wid] = s4;
        __syncthreads();
        if (t == 0){
            float tot = 0.f;
            #pragma unroll
            for (int w = 0; w < 8; w++) tot += wsum[w];
            atomicAdd(feat_next + row, tot * (1.0f/(float)L));
        }
    }
}

// ---------------- weight prep ----------------
__global__ void transpose_w_kernel(const float* __restrict__ gw, float* __restrict__ wt){
    int idx = blockIdx.x*256 + threadIdx.x;
    if (idx < 3*C*C*3){
        int lvl = idx / (C*C*3);
        int r   = idx % (C*C*3);
        int ci  = r / (3*C);
        int k   = (r % (3*C)) / C;
        int co  = r % C;
        wt[idx] = gw[(size_t)lvl*C*C*3 + ((size_t)co*C + ci)*3 + k];
    }
}
__global__ void prep2_kernel(const float* __restrict__ attn2_w, float* __restrict__ w2t,
                             float* __restrict__ feat){
    int idx = blockIdx.x*256 + threadIdx.x;
    if (idx < 2*32*C){
        int lvl = idx / (32*C);
        int r   = idx % (32*C);
        int ci  = r >> 7, co = r & 127;
        w2t[idx] = attn2_w[((size_t)lvl*C + co)*32 + ci];
    }
    if (idx < 2*B*C) feat[B*C + idx] = 0.f;   // zero feat levels 1,2
}

// ---------------- fused gates: conv3 + optional attn2 (phase1) + optional attn1 (phase3) ----
// phase1 (ATTN): det' = det*(1+sig(W2*a+b2)) -> yh
// phase2: z1 = conv3(cur)+bias; out = cur + sig(z1)*det'
// phase3 (A1): a_out = gelu(W1*out + b1)   (out staged through s_x)
#define P_X 132
#define SO_U  (C*P_X*4)                 // 67584: union (conv s_w 12KB / s_w2 16KB / s_w1 16KB)
#define SO_A  (SO_U + 32*C*4)           // 83968
#define GSM_ATTN  (SO_A + 32*C*4)       // 100352
#define GSM_PLAIN SO_A                  // 83968 (union must hold s_w1 for A1)

template<bool ATTN, bool A1>
__global__ __launch_bounds__(256, 2) void gatesf_kernel(
    const float* __restrict__ cur, const float* __restrict__ det_raw,
    const float* __restrict__ wt, const float* __restrict__ bias,
    const float* __restrict__ a_in, const float* __restrict__ w2t, const float* __restrict__ bias2,
    float* __restrict__ yh_out, float* __restrict__ out,
    const float* __restrict__ w1, const float* __restrict__ b1, float* __restrict__ a_out)
{
    extern __shared__ __align__(16) char smem[];
    float* s_x  = (float*)smem;              // [ci][132], j=0 <-> l0-1
    float* s_w  = (float*)(smem + SO_U);     // phase2: [8*3][128] chunks
    float* s_w2 = (float*)(smem + SO_U);     // phase1: [32][128]
    float* s_a  = (float*)(smem + SO_A);     // [32][128]
    int l0 = blockIdx.x*128, b = blockIdx.y, t = threadIdx.x;
    int wid = t >> 5, lane = t & 31, co0 = wid*16;
    int lq = lane*4;

    for (int idx = t; idx < C*130; idx += 256){
        int ci = idx/130, j = idx%130;
        int li = l0 + j - 1;
        float v = 0.f;
        if (li >= 0 && li < L) v = cur[((size_t)(b*C+ci))*L + li];
        s_x[ci*P_X + j] = v;
    }
    if (ATTN){
        for (int idx = t; idx < 32*C; idx += 256){
            int ci = idx >> 7, j = idx & 127;
            s_a[idx] = a_in[((size_t)(b*32+ci))*L + l0 + j];
        }
        for (int idx = t; idx < 32*C; idx += 256) s_w2[idx] = w2t[idx];
    }
    __syncthreads();

    // ---- phase 1 (ATTN): det' = det*(1+sig(W2*a+b2)) -> yh_out ----
    if (ATTN){
        unsigned long long acc2[8][4];
        #pragma unroll
        for (int c = 0; c < 8; c++)
            #pragma unroll
            for (int q = 0; q < 4; q++) acc2[c][q] = 0ull;
        #pragma unroll 4
        for (int ci = 0; ci < 32; ci++){
            float4 xv = *(const float4*)(&s_a[ci*C + lq]);
            unsigned long long p0 = pack2(xv.x, xv.x);
            unsigned long long p1 = pack2(xv.y, xv.y);
            unsigned long long p2 = pack2(xv.z, xv.z);
            unsigned long long p3 = pack2(xv.w, xv.w);
            const ulonglong2* wp = (const ulonglong2*)(&s_w2[ci*C + co0]);
            unsigned long long wr[8];
            ((ulonglong2*)wr)[0] = wp[0];
            ((ulonglong2*)wr)[1] = wp[1];
            ((ulonglong2*)wr)[2] = wp[2];
            ((ulonglong2*)wr)[3] = wp[3];
            #pragma unroll
            for (int c = 0; c < 8; c++){
                acc2[c][0] = fma2(wr[c], p0, acc2[c][0]);
                acc2[c][1] = fma2(wr[c], p1, acc2[c][1]);
                acc2[c][2] = fma2(wr[c], p2, acc2[c][2]);
                acc2[c][3] = fma2(wr[c], p3, acc2[c][3]);
            }
        }
        #pragma unroll
        for (int c = 0; c < 8; c++){
            int co = co0 + 2*c;
            float2 z[4];
            #pragma unroll
            for (int q = 0; q < 4; q++) z[q] = unpack2(acc2[c][q]);
            #pragma unroll
            for (int s = 0; s < 2; s++){
                float bv = __ldg(&bias2[co+s]);
                size_t idx = ((size_t)(b*C+co+s))*L + l0 + lq;
                float4 dv = *(const float4*)(det_raw + idx);
                dv.x *= 1.0f + sigmoid_f((s ? z[0].y : z[0].x) + bv);
                dv.y *= 1.0f + sigmoid_f((s ? z[1].y : z[1].x) + bv);
                dv.z *= 1.0f + sigmoid_f((s ? z[2].y : z[2].x) + bv);
                dv.w *= 1.0f + sigmoid_f((s ? z[3].y : z[3].x) + bv);
                *(float4*)(yh_out + idx) = dv;
            }
        }
    }

    // ---- phase 2: conv3 ----
    unsigned long long acc[8][4];
    #pragma unroll
    for (int c = 0; c < 8; c++)
        #pragma unroll
        for (int q = 0; q < 4; q++) acc[c][q] = 0ull;

    for (int ci0 = 0; ci0 < C; ci0 += 8){
        __syncthreads();
        for (int idx = t; idx < 8*3*C; idx += 256) s_w[idx] = wt[ci0*3*C + idx];
        __syncthreads();
        #pragma unroll
        for (int ci = 0; ci < 8; ci++){
            const float* xr = &s_x[(ci0+ci)*P_X + lq];
            float4 xv = *(const float4*)xr;
            float x4 = xr[4], x5 = xr[5];
            unsigned long long p[6];
            p[0] = pack2(xv.x, xv.x);
            p[1] = pack2(xv.y, xv.y);
            p[2] = pack2(xv.z, xv.z);
            p[3] = pack2(xv.w, xv.w);
            p[4] = pack2(x4, x4);
            p[5] = pack2(x5, x5);
            #pragma unroll
            for (int tap = 0; tap < 3; tap++){
                const ulonglong2* wp = (const ulonglong2*)(&s_w[(ci*3+tap)*C + co0]);
                unsigned long long wr[8];
                ((ulonglong2*)wr)[0] = wp[0];
                ((ulonglong2*)wr)[1] = wp[1];
                ((ulonglong2*)wr)[2] = wp[2];
                ((ulonglong2*)wr)[3] = wp[3];
                #pragma unroll
                for (int c = 0; c < 8; c++){
                    acc[c][0] = fma2(wr[c], p[tap],   acc[c][0]);
                    acc[c][1] = fma2(wr[c], p[tap+1], acc[c][1]);
                    acc[c][2] = fma2(wr[c], p[tap+2], acc[c][2]);
                    acc[c][3] = fma2(wr[c], p[tap+3], acc[c][3]);
                }
            }
        }
    }

    // guard s_x staging + s_w1 overwrite against last conv chunk readers
    if (A1) __syncthreads();

    // ---- epilogue: gate + write (+ stage out into s_x for phase 3) ----
    #pragma unroll
    for (int c = 0; c < 8; c++){
        int co = co0 + 2*c;
        float2 z[4];
        #pragma unroll
        for (int q = 0; q < 4; q++) z[q] = unpack2(acc[c][q]);
        #pragma unroll
        for (int s = 0; s < 2; s++){
            int cs = co + s;
            float bv = __ldg(&bias[cs]);
            size_t idx = ((size_t)(b*C+cs))*L + l0 + lq;
            const float* dsrc = ATTN ? yh_out : det_raw;
            float4 dv = *(const float4*)(dsrc + idx);
            const float* cr = &s_x[cs*P_X + lq + 1];
            float4 ov;
            ov.x = cr[0] + sigmoid_f((s ? z[0].y : z[0].x) + bv)*dv.x;
            ov.y = cr[1] + sigmoid_f((s ? z[1].y : z[1].x) + bv)*dv.y;
            ov.z = cr[2] + sigmoid_f((s ? z[2].y : z[2].x) + bv)*dv.z;
            ov.w = cr[3] + sigmoid_f((s ? z[3].y : z[3].x) + bv)*dv.w;
            *(float4*)(out + idx) = ov;
            if (A1){
                float* st = &s_x[cs*P_X + lq + 1];
                st[0] = ov.x; st[1] = ov.y; st[2] = ov.z; st[3] = ov.w;
            }
        }
    }

    // ---- phase 3 (A1): a_out = gelu(W1*out + b1), strided l for conflict-free LDS ----
    if (A1){
        float* s_w1 = s_w;
        for (int idx = t; idx < 32*C; idx += 256){
            int ci = idx >> 5, c2 = idx & 31;
            s_w1[idx] = w1[c2*C + ci];
        }
        __syncthreads();
        int c2b = wid*4;
        unsigned long long acc3[2][4];
        #pragma unroll
        for (int pc = 0; pc < 2; pc++)
            #pragma unroll
            for (int q = 0; q < 4; q++) acc3[pc][q] = 0ull;
        #pragma unroll 4
        for (int ci = 0; ci < C; ci++){
            ulonglong2 wv = *(const ulonglong2*)(&s_w1[ci*32 + c2b]);
            #pragma unroll
            for (int q = 0; q < 4; q++){
                float xv = s_x[ci*P_X + lane + 32*q + 1];
                unsigned long long p = pack2(xv, xv);
                acc3[0][q] = fma2(wv.x, p, acc3[0][q]);
                acc3[1][q] = fma2(wv.y, p, acc3[1][q]);
            }
        }
        #pragma unroll
        for (int pc = 0; pc < 2; pc++){
            int c2 = c2b + 2*pc;
            float b10 = __ldg(&b1[c2]);
            float b11 = __ldg(&b1[c2+1]);
            #pragma unroll
            for (int q = 0; q < 4; q++){
                float2 z = unpack2(acc3[pc][q]);
                size_t ix = ((size_t)(b*32 + c2))*L + l0 + lane + 32*q;
                a_out[ix]     = gelu_f(z.x + b10);
                a_out[ix + L] = gelu_f(z.y + b11);
            }
        }
    }
}

// ---------------- host launch ----------------
extern "C" void kernel_launch(void* const* d_in, const int* in_sizes, int n_in,
                              void* d_out, int out_size)
{
    const float* x       = (const float*)d_in[0];
    const float* stat_w  = (const float*)d_in[1];
    const float* stat_b  = (const float*)d_in[2];
    const float* wg1_w   = (const float*)d_in[3];
    const float* wg1_b   = (const float*)d_in[4];
    const float* wg2_w   = (const float*)d_in[5];
    const float* wg2_b   = (const float*)d_in[6];
    const float* gates_w = (const float*)d_in[7];
    const float* gates_b = (const float*)d_in[8];
    const float* attn1_w = (const float*)d_in[9];
    const float* attn1_b = (const float*)d_in[10];
    const float* attn2_w = (const float*)d_in[11];
    const float* attn2_b = (const float*)d_in[12];
    float* out = (float*)d_out;

    float *a1, *a2, *a3, *attn, *feat, *h1, *h2, *wt, *w2t;
    cudaGetSymbolAddress((void**)&a1,   g_a1);
    cudaGetSymbolAddress((void**)&a2,   g_a2);
    cudaGetSymbolAddress((void**)&a3,   g_a3);
    cudaGetSymbolAddress((void**)&attn, g_attn);
    cudaGetSymbolAddress((void**)&feat, g_feat);
    cudaGetSymbolAddress((void**)&h1,   g_h1);
    cudaGetSymbolAddress((void**)&h2,   g_h2);
    cudaGetSymbolAddress((void**)&wt,   g_wt);
    cudaGetSymbolAddress((void**)&w2t,  g_w2t);

    float* yl  = out;
    float* yh0 = out + NYL;
    float* yh1 = out + 2*NYL;
    float* yh2 = out + 3*NYL;
    float* scal= out + 4*NYL;
    float* lo_all = out + 4*NYL + 2;
    float* hi_all = lo_all + 3*B*FL;

    cudaFuncSetAttribute((const void*)gatesf_kernel<false,true>,  cudaFuncAttributeMaxDynamicSharedMemorySize, GSM_PLAIN);
    cudaFuncSetAttribute((const void*)gatesf_kernel<true,true>,   cudaFuncAttributeMaxDynamicSharedMemorySize, GSM_ATTN);
    cudaFuncSetAttribute((const void*)gatesf_kernel<true,false>,  cudaFuncAttributeMaxDynamicSharedMemorySize, GSM_ATTN);

    transpose_w_kernel<<<(3*C*C*3 + 255)/256, 256>>>(gates_w, wt);
    prep2_kernel<<<(2*32*C + 255)/256, 256>>>(attn2_w, w2t, feat);

    const float* ain[3]  = {x, a1, a2};
    float*       aout[3] = {a1, a2, a3};
    float*       dets[3] = {yh0, yh1, yh2};

    mean_kernel<<<NROW, 256>>>(x, feat);
    for (int lvl = 0; lvl < 3; lvl++){
        float* lo = lo_all + lvl*B*FL;
        float* hi = hi_all + lvl*B*FL;
        const float* f = feat + lvl*B*C;
        mlp_l1<<<dim3(DIM/8, B), 256>>>(f, stat_w, stat_b, h1);
        mlp_l2<<<dim3(2*DIM/8, B), 256>>>(h1, wg1_w, wg1_b, h2);
        mlp_l3<<<B, 576>>>(h2, wg2_w, wg2_b, lo, hi);
        float* fnext = (lvl < 2) ? (feat + (lvl+1)*B*C) : nullptr;
        dw_kernel<<<dim3(L/DTL, NROW), 256>>>(ain[lvl], lo, hi, aout[lvl], dets[lvl], fnext);
    }

    ortho_kernel<<<1, 32>>>(lo_all + 2*B*FL, scal);

    // i = 2: gates (no attn2) + fused attn1 for level 1 -> attn
    gatesf_kernel<false,true><<<dim3(L/128, B), 256, GSM_PLAIN>>>(
        a3, yh2, wt + 2*C*3*C, gates_b + 2*C,
        nullptr, nullptr, nullptr, nullptr, a1,
        attn1_w + 1*(C/4)*C, attn1_b + (C/4), attn);
    // i = 1: gates + attn2(level 1) + fused attn1 for level 0 -> attn
    gatesf_kernel<true,true><<<dim3(L/128, B), 256, GSM_ATTN>>>(
        a1, yh1, wt + 1*C*3*C, gates_b + 1*C,
        attn, w2t + 32*C, attn2_b + C, yh1, a2,
        attn1_w, attn1_b, attn);
    // i = 0: gates + attn2(level 0) -> yl
    gatesf_kernel<true,false><<<dim3(L/128, B), 256, GSM_ATTN>>>(
        a2, yh0, wt, gates_b,
        attn, w2t, attn2_b, yh0, yl,
        nullptr, nullptr, nullptr);
}

// round 13
// speedup vs baseline: 1.5126x; 1.1286x over previous
#include <cuda_runtime.h>
#include <math.h>
#include <stdint.h>

#define B 32
#define C 128
#define L 4096
#define NROW (B*C)
#define BCL (B*C*L)            // 16777216
#define FL 9
#define DIM 512
#define NYL ((size_t)BCL)

// ---------------- scratch (device globals; no allocation) ----------------
__device__ float g_a1[BCL];
__device__ float g_a2[BCL];
__device__ float g_a3[BCL];
__device__ float g_attn[B*(C/4)*L];
__device__ float g_feat[3*B*C];          // per-level feature means
__device__ float g_h1[B*DIM];
__device__ float g_h2[B*2*DIM];
__device__ __align__(16) float g_wt[3*C*3*C];   // gates weights [lvl][ci][k][co]
__device__ float g_w2t[2*32*C];          // attn2 weights [lvl][ci][co]

__device__ __forceinline__ float gelu_f(float x){
    return 0.5f*x*(1.0f+erff(x*0.7071067811865476f));
}
__device__ __forceinline__ float sigmoid_f(float x){
    return 1.0f/(1.0f+expf(-x));
}

// ---- packed f32x2 helpers (Blackwell FFMA2) ----
__device__ __forceinline__ unsigned long long pack2(float lo, float hi){
    unsigned long long r;
    asm("mov.b64 %0, {%1, %2};" : "=l"(r) : "f"(lo), "f"(hi));
    return r;
}
__device__ __forceinline__ unsigned long long fma2(unsigned long long a, unsigned long long b, unsigned long long c){
    unsigned long long d;
    asm("fma.rn.f32x2 %0, %1, %2, %3;" : "=l"(d) : "l"(a), "l"(b), "l"(c));
    return d;
}
__device__ __forceinline__ float2 unpack2(unsigned long long v){
    float2 f;
    asm("mov.b64 {%0, %1}, %2;" : "=f"(f.x), "=f"(f.y) : "l"(v));
    return f;
}

// ---- cp.async helpers (baseline sm_80 PTX) ----
__device__ __forceinline__ uint32_t smem_u32(const void* p){
    uint32_t a;
    asm("{ .reg .u64 t; cvta.to.shared.u64 t, %1; cvt.u32.u64 %0, t; }" : "=r"(a) : "l"(p));
    return a;
}
__device__ __forceinline__ void cp16(uint32_t dst, const void* src){
    asm volatile("cp.async.ca.shared.global [%0], [%1], 16;" :: "r"(dst), "l"(src) : "memory");
}
__device__ __forceinline__ void cp_commit(){
    asm volatile("cp.async.commit_group;" ::: "memory");
}
template<int N>
__device__ __forceinline__ void cp_wait(){
    asm volatile("cp.async.wait_group %0;" :: "n"(N) : "memory");
}

// ---------------- mean over L (level 0 only) ----------------
__global__ __launch_bounds__(256) void mean_kernel(const float* __restrict__ x,
                                                   float* __restrict__ feat){
    int row = blockIdx.x;
    const float4* p = (const float4*)(x + (size_t)row*L);
    float s = 0.f;
    for (int i = threadIdx.x; i < L/4; i += 256){
        float4 v = p[i];
        s += (v.x+v.y)+(v.z+v.w);
    }
    __shared__ float red[256];
    red[threadIdx.x] = s; __syncthreads();
    for (int off = 128; off > 0; off >>= 1){
        if (threadIdx.x < off) red[threadIdx.x] += red[threadIdx.x+off];
        __syncthreads();
    }
    if (threadIdx.x == 0) feat[row] = red[0] * (1.0f/(float)L);
}

// ---------------- MLP layers (warp-per-output GEMV) ----------------
__global__ __launch_bounds__(256) void mlp_l1(const float* __restrict__ feat,
                                              const float* __restrict__ sw, const float* __restrict__ sb,
                                              float* __restrict__ h1){
    int b = blockIdx.y;
    int j = blockIdx.x*8 + (threadIdx.x >> 5);
    int lane = threadIdx.x & 31;
    float4 w = ((const float4*)(sw + (size_t)j*C))[lane];
    float4 f = ((const float4*)(feat + b*C))[lane];
    float s = w.x*f.x + w.y*f.y + w.z*f.z + w.w*f.w;
    #pragma unroll
    for (int off = 16; off > 0; off >>= 1) s += __shfl_xor_sync(0xffffffffu, s, off);
    if (lane == 0) h1[b*DIM + j] = gelu_f(s + sb[j]);
}

__global__ __launch_bounds__(256) void mlp_l2(const float* __restrict__ h1,
                                              const float* __restrict__ w1, const float* __restrict__ b1,
                                              float* __restrict__ h2){
    __shared__ __align__(16) float sh[DIM];
    int b = blockIdx.y, t = threadIdx.x;
    for (int i = t; i < DIM/4; i += 256)
        ((float4*)sh)[i] = ((const float4*)(h1 + b*DIM))[i];
    __syncthreads();
    int j = blockIdx.x*8 + (t >> 5);
    int lane = t & 31;
    const float4* wr = (const float4*)(w1 + (size_t)j*DIM);
    float s = 0.f;
    #pragma unroll
    for (int i = 0; i < 4; i++){
        float4 w = wr[i*32 + lane];
        float4 f = ((const float4*)sh)[i*32 + lane];
        s += w.x*f.x + w.y*f.y + w.z*f.z + w.w*f.w;
    }
    #pragma unroll
    for (int off = 16; off > 0; off >>= 1) s += __shfl_xor_sync(0xffffffffu, s, off);
    if (lane == 0) h2[b*2*DIM + j] = gelu_f(s + b1[j]);
}

__global__ __launch_bounds__(576) void mlp_l3(const float* __restrict__ h2,
                                              const float* __restrict__ w2, const float* __restrict__ b2,
                                              float* __restrict__ lo, float* __restrict__ hi){
    __shared__ __align__(16) float sh[2*DIM];
    int b = blockIdx.x, t = threadIdx.x;
    for (int i = t; i < 2*DIM/4; i += 576)
        ((float4*)sh)[i] = ((const float4*)(h2 + b*2*DIM))[i];
    __syncthreads();
    int j = t >> 5, lane = t & 31;     // 18 warps
    const float4* wr = (const float4*)(w2 + (size_t)j*2*DIM);
    float s = 0.f;
    #pragma unroll
    for (int i = 0; i < 8; i++){
        float4 w = wr[i*32 + lane];
        float4 f = ((const float4*)sh)[i*32 + lane];
        s += w.x*f.x + w.y*f.y + w.z*f.z + w.w*f.w;
    }
    #pragma unroll
    for (int off = 16; off > 0; off >>= 1) s += __shfl_xor_sync(0xffffffffu, s, off);
    if (lane == 0){
        float v = s + b2[j];
        if (j < FL) lo[b*FL + j] = v;
        else        hi[b*FL + (j-FL)] = v;
    }
}

// ---------------- ortho loss (last level only) + energy=0 ----------------
__global__ void ortho_kernel(const float* __restrict__ lo, float* __restrict__ out_scalars){
    int b = threadIdx.x;
    float v[FL]; float ss = 0.f;
    #pragma unroll
    for (int k = 0; k < FL; k++){ v[k] = lo[b*FL+k]; ss += v[k]*v[k]; }
    float den = sqrtf(ss) + 1e-8f;
    float S = 0.f, sq = 0.f;
    #pragma unroll
    for (int k = 0; k < FL; k++){
        float n = v[k]/den;
        S  += fabsf(n);
        sq += n*n;
    }
    float S2  = S*S;
    float amp = fabsf(sq - 1.0f);
    float sm  = fabsf(v[0]);
    #pragma unroll
    for (int k = 1; k < FL; k++) sm += fabsf(v[k]-v[k-1]);
    sm += fabsf(v[FL-1]);
    #pragma unroll
    for (int off = 16; off > 0; off >>= 1){
        S2  += __shfl_xor_sync(0xffffffffu, S2,  off);
        amp += __shfl_xor_sync(0xffffffffu, amp, off);
        sm  += __shfl_xor_sync(0xffffffffu, sm,  off);
    }
    if (b == 0){
        float shift  = 3.0f * S2 / (32.0f*81.0f);
        float ampm   = amp / 32.0f;
        float smm    = sm / (32.0f*10.0f);
        out_scalars[0] = 0.01f*(shift + ampm) + 0.1f*smm;
        out_scalars[1] = 0.0f;
    }
}

// ---------------- per-sample depthwise 9-tap (edge pad) + mean accumulate ----------------
#define DTL 1024
__global__ __launch_bounds__(256) void dw_kernel(
    const float* __restrict__ x, const float* __restrict__ lo, const float* __restrict__ hi,
    float* __restrict__ out_a, float* __restrict__ out_d, float* __restrict__ feat_next)
{
    int row = blockIdx.y;
    int b   = row >> 7;
    int l0  = blockIdx.x * DTL;
    __shared__ __align__(16) float s[DTL + 16];
    __shared__ float wsum[8];
    const float* xr = x + (size_t)row * L;
    int t = threadIdx.x, lane = t & 31, wid = t >> 5;
    {
        const float4* xv = (const float4*)(xr + l0);
        ((float4*)(s + 4))[t] = xv[t];
    }
    if (t < 4){
        int li = l0 - 4 + t;
        s[t] = xr[max(li, 0)];
        int ri = l0 + DTL + t;
        s[DTL + 4 + t] = xr[min(ri, L-1)];
    }
    unsigned long long pf[FL];
    #pragma unroll
    for (int k = 0; k < FL; k++) pf[k] = pack2(__ldg(&lo[b*FL+k]), __ldg(&hi[b*FL+k]));
    __syncthreads();

    int i0 = t * 4;
    float win[12];
    #pragma unroll
    for (int j = 0; j < 12; j++) win[j] = s[i0 + j];
    unsigned long long acc[4];
    #pragma unroll
    for (int p = 0; p < 4; p++) acc[p] = 0ull;
    #pragma unroll
    for (int k = 0; k < FL; k++){
        #pragma unroll
        for (int p = 0; p < 4; p++){
            unsigned long long vv = pack2(win[p+k], win[p+k]);
            acc[p] = fma2(vv, pf[k], acc[p]);
        }
    }
    float4 ra, rd;
    float2 f0 = unpack2(acc[0]), f1 = unpack2(acc[1]), f2 = unpack2(acc[2]), f3 = unpack2(acc[3]);
    ra.x = f0.x; ra.y = f1.x; ra.z = f2.x; ra.w = f3.x;
    rd.x = f0.y; rd.y = f1.y; rd.z = f2.y; rd.w = f3.y;
    size_t idx = (size_t)row*L + l0 + i0;
    *(float4*)(out_a + idx) = ra;
    *(float4*)(out_d + idx) = rd;

    if (feat_next){
        float s4 = (ra.x + ra.y) + (ra.z + ra.w);
        #pragma unroll
        for (int off = 16; off > 0; off >>= 1) s4 += __shfl_xor_sync(0xffffffffu, s4, off);
        if (lane == 0) wsum[wid] = s4;
        __syncthreads();
        if (t == 0){
            float tot = 0.f;
            #pragma unroll
            for (int w = 0; w < 8; w++) tot += wsum[w];
            atomicAdd(feat_next + row, tot * (1.0f/(float)L));
        }
    }
}

// ---------------- weight prep ----------------
__global__ void transpose_w_kernel(const float* __restrict__ gw, float* __restrict__ wt){
    int idx = blockIdx.x*256 + threadIdx.x;
    if (idx < 3*C*C*3){
        int lvl = idx / (C*C*3);
        int r   = idx % (C*C*3);
        int ci  = r / (3*C);
        int k   = (r % (3*C)) / C;
        int co  = r % C;
        wt[idx] = gw[(size_t)lvl*C*C*3 + ((size_t)co*C + ci)*3 + k];
    }
}
__global__ void prep2_kernel(const float* __restrict__ attn2_w, float* __restrict__ w2t,
                             float* __restrict__ feat){
    int idx = blockIdx.x*256 + threadIdx.x;
    if (idx < 2*32*C){
        int lvl = idx / (32*C);
        int r   = idx % (32*C);
        int ci  = r >> 7, co = r & 127;
        w2t[idx] = attn2_w[((size_t)lvl*C + co)*32 + ci];
    }
    if (idx < 2*B*C) feat[B*C + idx] = 0.f;   // zero feat levels 1,2
}

// ---------------- fused gates: conv3 (cp.async weight pipeline) + attn2 + attn1 ----
// phase1 (ATTN): det' = det*(1+sig(W2*a+b2)) -> yh
// phase2: z1 = conv3(cur)+bias; out = cur + sig(z1)*det'
// phase3 (A1): a_out = gelu(W1*out + b1)   (out staged through s_x)
#define P_X 132
#define WCH (3*8*C)                     // 3072 floats / chunk
#define SO_U  (C*P_X*4)                 // 67584: union (wbuf double 24KB / s_w2 16KB / s_w1 16KB)
#define WBUF_SZ (2*WCH*4)               // 24576
#define SO_A  (SO_U + WBUF_SZ)          // 92160
#define GSM_ATTN  (SO_A + 32*C*4)       // 108544
#define GSM_PLAIN SO_A                  // 92160

template<bool ATTN, bool A1>
__global__ __launch_bounds__(256, 2) void gatesf_kernel(
    const float* __restrict__ cur, const float* __restrict__ det_raw,
    const float* __restrict__ wt, const float* __restrict__ bias,
    const float* __restrict__ a_in, const float* __restrict__ w2t, const float* __restrict__ bias2,
    float* __restrict__ yh_out, float* __restrict__ out,
    const float* __restrict__ w1, const float* __restrict__ b1, float* __restrict__ a_out)
{
    extern __shared__ __align__(16) char smem[];
    float* s_x  = (float*)smem;              // [ci][132], j=0 <-> l0-1
    float* s_w2 = (float*)(smem + SO_U);     // phase1: [32][128] (union w/ wbuf)
    float* s_a  = (float*)(smem + SO_A);     // [32][128]
    uint32_t wb_base = smem_u32(smem + SO_U);
    int l0 = blockIdx.x*128, b = blockIdx.y, t = threadIdx.x;
    int wid = t >> 5, lane = t & 31, co0 = wid*16;
    int lq = lane*4;

    // ---- fill s_x: interior (div-free), then edges ----
    #pragma unroll 4
    for (int k = 0; k < 64; k++){
        int idx = t + k*256;
        int ci = idx >> 7, jj = idx & 127;
        s_x[ci*P_X + jj + 1] = cur[((size_t)(b*C+ci))*L + l0 + jj];
    }
    {
        int ci = t >> 1;
        size_t row = (size_t)(b*C+ci)*L;
        if ((t & 1) == 0){
            s_x[ci*P_X] = (l0 > 0) ? cur[row + l0 - 1] : 0.f;
        } else {
            s_x[ci*P_X + 129] = (l0 + 128 < L) ? cur[row + l0 + 128] : 0.f;
        }
    }
    if (ATTN){
        for (int idx = t; idx < 32*C; idx += 256){
            int ci = idx >> 7, j = idx & 127;
            s_a[idx] = a_in[((size_t)(b*32+ci))*L + l0 + j];
        }
        for (int idx = t; idx < 32*C; idx += 256) s_w2[idx] = w2t[idx];
    }
    __syncthreads();

    // ---- phase 1 (ATTN): det' = det*(1+sig(W2*a+b2)) -> yh_out ----
    if (ATTN){
        unsigned long long acc2[8][4];
        #pragma unroll
        for (int c = 0; c < 8; c++)
            #pragma unroll
            for (int q = 0; q < 4; q++) acc2[c][q] = 0ull;
        #pragma unroll 4
        for (int ci = 0; ci < 32; ci++){
            float4 xv = *(const float4*)(&s_a[ci*C + lq]);
            unsigned long long p0 = pack2(xv.x, xv.x);
            unsigned long long p1 = pack2(xv.y, xv.y);
            unsigned long long p2 = pack2(xv.z, xv.z);
            unsigned long long p3 = pack2(xv.w, xv.w);
            const ulonglong2* wp = (const ulonglong2*)(&s_w2[ci*C + co0]);
            unsigned long long wr[8];
            ((ulonglong2*)wr)[0] = wp[0];
            ((ulonglong2*)wr)[1] = wp[1];
            ((ulonglong2*)wr)[2] = wp[2];
            ((ulonglong2*)wr)[3] = wp[3];
            #pragma unroll
            for (int c = 0; c < 8; c++){
                acc2[c][0] = fma2(wr[c], p0, acc2[c][0]);
                acc2[c][1] = fma2(wr[c], p1, acc2[c][1]);
                acc2[c][2] = fma2(wr[c], p2, acc2[c][2]);
                acc2[c][3] = fma2(wr[c], p3, acc2[c][3]);
            }
        }
        #pragma unroll
        for (int c = 0; c < 8; c++){
            int co = co0 + 2*c;
            float2 z[4];
            #pragma unroll
            for (int q = 0; q < 4; q++) z[q] = unpack2(acc2[c][q]);
            #pragma unroll
            for (int s = 0; s < 2; s++){
                float bv = __ldg(&bias2[co+s]);
                size_t idx = ((size_t)(b*C+co+s))*L + l0 + lq;
                float4 dv = *(const float4*)(det_raw + idx);
                dv.x *= 1.0f + sigmoid_f((s ? z[0].y : z[0].x) + bv);
                dv.y *= 1.0f + sigmoid_f((s ? z[1].y : z[1].x) + bv);
                dv.z *= 1.0f + sigmoid_f((s ? z[2].y : z[2].x) + bv);
                dv.w *= 1.0f + sigmoid_f((s ? z[3].y : z[3].x) + bv);
                *(float4*)(yh_out + idx) = dv;
            }
        }
        __syncthreads();   // s_w2 reads done before wbuf prefetch overwrites
    }

    // ---- phase 2: conv3 with double-buffered cp.async weight pipeline ----
    unsigned long long acc[8][4];
    #pragma unroll
    for (int c = 0; c < 8; c++)
        #pragma unroll
        for (int q = 0; q < 4; q++) acc[c][q] = 0ull;

    // prefetch chunk 0 into buffer 0
    {
        uint32_t dst = wb_base;
        const char* src = (const char*)wt;
        cp16(dst + t*16,         src + t*16);
        cp16(dst + (t+256)*16,   src + (t+256)*16);
        cp16(dst + (t+512)*16,   src + (t+512)*16);
        cp_commit();
    }

    for (int ch = 0; ch < 16; ch++){
        if (ch) __syncthreads();                  // prev chunk compute done (protects wbuf overwrite)
        if (ch < 15){
            uint32_t dst = wb_base + (((ch+1)&1) ? (uint32_t)(WCH*4) : 0u);
            const char* src = (const char*)(wt + (ch+1)*WCH);
            cp16(dst + t*16,       src + t*16);
            cp16(dst + (t+256)*16, src + (t+256)*16);
            cp16(dst + (t+512)*16, src + (t+512)*16);
            cp_commit();
            cp_wait<1>();
        } else {
            cp_wait<0>();
        }
        __syncthreads();                          // chunk ch data visible to all
        const float* s_w = (const float*)(smem + SO_U + ((ch&1) ? WCH*4 : 0));
        int ci0 = ch*8;
        #pragma unroll
        for (int ci = 0; ci < 8; ci++){
            const float* xr = &s_x[(ci0+ci)*P_X + lq];
            float4 xv = *(const float4*)xr;
            float x4 = xr[4], x5 = xr[5];
            unsigned long long p[6];
            p[0] = pack2(xv.x, xv.x);
            p[1] = pack2(xv.y, xv.y);
            p[2] = pack2(xv.z, xv.z);
            p[3] = pack2(xv.w, xv.w);
            p[4] = pack2(x4, x4);
            p[5] = pack2(x5, x5);
            #pragma unroll
            for (int tap = 0; tap < 3; tap++){
                const ulonglong2* wp = (const ulonglong2*)(&s_w[(ci*3+tap)*C + co0]);
                unsigned long long wr[8];
                ((ulonglong2*)wr)[0] = wp[0];
                ((ulonglong2*)wr)[1] = wp[1];
                ((ulonglong2*)wr)[2] = wp[2];
                ((ulonglong2*)wr)[3] = wp[3];
                #pragma unroll
                for (int c = 0; c < 8; c++){
                    acc[c][0] = fma2(wr[c], p[tap],   acc[c][0]);
                    acc[c][1] = fma2(wr[c], p[tap+1], acc[c][1]);
                    acc[c][2] = fma2(wr[c], p[tap+2], acc[c][2]);
                    acc[c][3] = fma2(wr[c], p[tap+3], acc[c][3]);
                }
            }
        }
    }

    // guard s_x staging + s_w1 overwrite against last chunk readers
    if (A1) __syncthreads();

    // ---- epilogue: gate + write (+ stage out into s_x for phase 3) ----
    #pragma unroll
    for (int c = 0; c < 8; c++){
        int co = co0 + 2*c;
        float2 z[4];
        #pragma unroll
        for (int q = 0; q < 4; q++) z[q] = unpack2(acc[c][q]);
        #pragma unroll
        for (int s = 0; s < 2; s++){
            int cs = co + s;
            float bv = __ldg(&bias[cs]);
            size_t idx = ((size_t)(b*C+cs))*L + l0 + lq;
            const float* dsrc = ATTN ? yh_out : det_raw;
            float4 dv = *(const float4*)(dsrc + idx);
            const float* cr = &s_x[cs*P_X + lq + 1];
            float4 ov;
            ov.x = cr[0] + sigmoid_f((s ? z[0].y : z[0].x) + bv)*dv.x;
            ov.y = cr[1] + sigmoid_f((s ? z[1].y : z[1].x) + bv)*dv.y;
            ov.z = cr[2] + sigmoid_f((s ? z[2].y : z[2].x) + bv)*dv.z;
            ov.w = cr[3] + sigmoid_f((s ? z[3].y : z[3].x) + bv)*dv.w;
            *(float4*)(out + idx) = ov;
            if (A1){
                float* st = &s_x[cs*P_X + lq + 1];
                st[0] = ov.x; st[1] = ov.y; st[2] = ov.z; st[3] = ov.w;
            }
        }
    }

    // ---- phase 3 (A1): a_out = gelu(W1*out + b1), strided l for conflict-free LDS ----
    if (A1){
        float* s_w1 = (float*)(smem + SO_U);   // wbuf region free now
        for (int idx = t; idx < 32*C; idx += 256){
            int ci = idx >> 5, c2 = idx & 31;
            s_w1[idx] = w1[c2*C + ci];
        }
        __syncthreads();
        int c2b = wid*4;
        unsigned long long acc3[2][4];
        #pragma unroll
        for (int pc = 0; pc < 2; pc++)
            #pragma unroll
            for (int q = 0; q < 4; q++) acc3[pc][q] = 0ull;
        #pragma unroll 4
        for (int ci = 0; ci < C; ci++){
            ulonglong2 wv = *(const ulonglong2*)(&s_w1[ci*32 + c2b]);
            #pragma unroll
            for (int q = 0; q < 4; q++){
                float xv = s_x[ci*P_X + lane + 32*q + 1];
                unsigned long long p = pack2(xv, xv);
                acc3[0][q] = fma2(wv.x, p, acc3[0][q]);
                acc3[1][q] = fma2(wv.y, p, acc3[1][q]);
            }
        }
        #pragma unroll
        for (int pc = 0; pc < 2; pc++){
            int c2 = c2b + 2*pc;
            float b10 = __ldg(&b1[c2]);
            float b11 = __ldg(&b1[c2+1]);
            #pragma unroll
            for (int q = 0; q < 4; q++){
                float2 z = unpack2(acc3[pc][q]);
                size_t ix = ((size_t)(b*32 + c2))*L + l0 + lane + 32*q;
                a_out[ix]     = gelu_f(z.x + b10);
                a_out[ix + L] = gelu_f(z.y + b11);
            }
        }
    }
}

// ---------------- host launch ----------------
extern "C" void kernel_launch(void* const* d_in, const int* in_sizes, int n_in,
                              void* d_out, int out_size)
{
    const float* x       = (const float*)d_in[0];
    const float* stat_w  = (const float*)d_in[1];
    const float* stat_b  = (const float*)d_in[2];
    const float* wg1_w   = (const float*)d_in[3];
    const float* wg1_b   = (const float*)d_in[4];
    const float* wg2_w   = (const float*)d_in[5];
    const float* wg2_b   = (const float*)d_in[6];
    const float* gates_w = (const float*)d_in[7];
    const float* gates_b = (const float*)d_in[8];
    const float* attn1_w = (const float*)d_in[9];
    const float* attn1_b = (const float*)d_in[10];
    const float* attn2_w = (const float*)d_in[11];
    const float* attn2_b = (const float*)d_in[12];
    float* out = (float*)d_out;

    float *a1, *a2, *a3, *attn, *feat, *h1, *h2, *wt, *w2t;
    cudaGetSymbolAddress((void**)&a1,   g_a1);
    cudaGetSymbolAddress((void**)&a2,   g_a2);
    cudaGetSymbolAddress((void**)&a3,   g_a3);
    cudaGetSymbolAddress((void**)&attn, g_attn);
    cudaGetSymbolAddress((void**)&feat, g_feat);
    cudaGetSymbolAddress((void**)&h1,   g_h1);
    cudaGetSymbolAddress((void**)&h2,   g_h2);
    cudaGetSymbolAddress((void**)&wt,   g_wt);
    cudaGetSymbolAddress((void**)&w2t,  g_w2t);

    float* yl  = out;
    float* yh0 = out + NYL;
    float* yh1 = out + 2*NYL;
    float* yh2 = out + 3*NYL;
    float* scal= out + 4*NYL;
    float* lo_all = out + 4*NYL + 2;
    float* hi_all = lo_all + 3*B*FL;

    cudaFuncSetAttribute((const void*)gatesf_kernel<false,true>,  cudaFuncAttributeMaxDynamicSharedMemorySize, GSM_PLAIN);
    cudaFuncSetAttribute((const void*)gatesf_kernel<true,true>,   cudaFuncAttributeMaxDynamicSharedMemorySize, GSM_ATTN);
    cudaFuncSetAttribute((const void*)gatesf_kernel<true,false>,  cudaFuncAttributeMaxDynamicSharedMemorySize, GSM_ATTN);

    transpose_w_kernel<<<(3*C*C*3 + 255)/256, 256>>>(gates_w, wt);
    prep2_kernel<<<(2*32*C + 255)/256, 256>>>(attn2_w, w2t, feat);

    const float* ain[3]  = {x, a1, a2};
    float*       aout[3] = {a1, a2, a3};
    float*       dets[3] = {yh0, yh1, yh2};

    mean_kernel<<<NROW, 256>>>(x, feat);
    for (int lvl = 0; lvl < 3; lvl++){
        float* lo = lo_all + lvl*B*FL;
        float* hi = hi_all + lvl*B*FL;
        const float* f = feat + lvl*B*C;
        mlp_l1<<<dim3(DIM/8, B), 256>>>(f, stat_w, stat_b, h1);
        mlp_l2<<<dim3(2*DIM/8, B), 256>>>(h1, wg1_w, wg1_b, h2);
        mlp_l3<<<B, 576>>>(h2, wg2_w, wg2_b, lo, hi);
        float* fnext = (lvl < 2) ? (feat + (lvl+1)*B*C) : nullptr;
        dw_kernel<<<dim3(L/DTL, NROW), 256>>>(ain[lvl], lo, hi, aout[lvl], dets[lvl], fnext);
    }

    ortho_kernel<<<1, 32>>>(lo_all + 2*B*FL, scal);

    // i = 2: gates (no attn2) + fused attn1 for level 1 -> attn
    gatesf_kernel<false,true><<<dim3(L/128, B), 256, GSM_PLAIN>>>(
        a3, yh2, wt + 2*C*3*C, gates_b + 2*C,
        nullptr, nullptr, nullptr, nullptr, a1,
        attn1_w + 1*(C/4)*C, attn1_b + (C/4), attn);
    // i = 1: gates + attn2(level 1) + fused attn1 for level 0 -> attn
    gatesf_kernel<true,true><<<dim3(L/128, B), 256, GSM_ATTN>>>(
        a1, yh1, wt + 1*C*3*C, gates_b + 1*C,
        attn, w2t + 32*C, attn2_b + C, yh1, a2,
        attn1_w, attn1_b, attn);
    // i = 0: gates + attn2(level 0) -> yl
    gatesf_kernel<true,false><<<dim3(L/128, B), 256, GSM_ATTN>>>(
        a2, yh0, wt, gates_b,
        attn, w2t, attn2_b, yh0, yl,
        nullptr, nullptr, nullptr);
}

// round 14
// speedup vs baseline: 1.5717x; 1.0391x over previous
#include <cuda_runtime.h>
#include <math.h>
#include <stdint.h>

#define B 32
#define C 128
#define L 4096
#define NROW (B*C)
#define BCL (B*C*L)            // 16777216
#define FL 9
#define DIM 512
#define NYL ((size_t)BCL)

// ---------------- scratch (device globals; no allocation) ----------------
__device__ float g_a1[BCL];
__device__ float g_a2[BCL];
__device__ float g_a3[BCL];
__device__ float g_attn[B*(C/4)*L];
__device__ float g_feat[3*B*C];          // per-level feature means
__device__ float g_h1[B*DIM];
__device__ float g_h2[B*2*DIM];
__device__ __align__(16) uint32_t g_wt2[3*24*2048];  // tf32 gates weights [lvl][tap*8+ch][co][16]
__device__ float g_w2t[2*32*C];          // attn2 weights [lvl][ci][co]

__device__ __forceinline__ float gelu_f(float x){
    return 0.5f*x*(1.0f+erff(x*0.7071067811865476f));
}
__device__ __forceinline__ float sigmoid_f(float x){
    return 1.0f/(1.0f+expf(-x));
}

// ---- packed f32x2 helpers (Blackwell FFMA2) ----
__device__ __forceinline__ unsigned long long pack2(float lo, float hi){
    unsigned long long r;
    asm("mov.b64 %0, {%1, %2};" : "=l"(r) : "f"(lo), "f"(hi));
    return r;
}
__device__ __forceinline__ unsigned long long fma2(unsigned long long a, unsigned long long b, unsigned long long c){
    unsigned long long d;
    asm("fma.rn.f32x2 %0, %1, %2, %3;" : "=l"(d) : "l"(a), "l"(b), "l"(c));
    return d;
}
__device__ __forceinline__ float2 unpack2(unsigned long long v){
    float2 f;
    asm("mov.b64 {%0, %1}, %2;" : "=f"(f.x), "=f"(f.y) : "l"(v));
    return f;
}

// ---- cp.async + mma helpers (baseline PTX) ----
__device__ __forceinline__ uint32_t smem_u32(const void* p){
    uint32_t a;
    asm("{ .reg .u64 t; cvta.to.shared.u64 t, %1; cvt.u32.u64 %0, t; }" : "=r"(a) : "l"(p));
    return a;
}
__device__ __forceinline__ void cp16(uint32_t dst, const void* src){
    asm volatile("cp.async.ca.shared.global [%0], [%1], 16;" :: "r"(dst), "l"(src) : "memory");
}
__device__ __forceinline__ void cp_commit(){
    asm volatile("cp.async.commit_group;" ::: "memory");
}
template<int N>
__device__ __forceinline__ void cp_wait(){
    asm volatile("cp.async.wait_group %0;" :: "n"(N) : "memory");
}
__device__ __forceinline__ void mma_tf32(float* d, uint32_t a0, uint32_t a1, uint32_t a2, uint32_t a3,
                                         uint32_t b0, uint32_t b1){
    asm volatile("mma.sync.aligned.m16n8k8.row.col.f32.tf32.tf32.f32 "
        "{%0,%1,%2,%3}, {%4,%5,%6,%7}, {%8,%9}, {%0,%1,%2,%3};"
        : "+f"(d[0]), "+f"(d[1]), "+f"(d[2]), "+f"(d[3])
        : "r"(a0), "r"(a1), "r"(a2), "r"(a3), "r"(b0), "r"(b1));
}

// ---------------- mean over L (level 0 only) ----------------
__global__ __launch_bounds__(256) void mean_kernel(const float* __restrict__ x,
                                                   float* __restrict__ feat){
    int row = blockIdx.x;
    const float4* p = (const float4*)(x + (size_t)row*L);
    float s = 0.f;
    for (int i = threadIdx.x; i < L/4; i += 256){
        float4 v = p[i];
        s += (v.x+v.y)+(v.z+v.w);
    }
    __shared__ float red[256];
    red[threadIdx.x] = s; __syncthreads();
    for (int off = 128; off > 0; off >>= 1){
        if (threadIdx.x < off) red[threadIdx.x] += red[threadIdx.x+off];
        __syncthreads();
    }
    if (threadIdx.x == 0) feat[row] = red[0] * (1.0f/(float)L);
}

// ---------------- MLP layers (warp-per-output GEMV) ----------------
__global__ __launch_bounds__(256) void mlp_l1(const float* __restrict__ feat,
                                              const float* __restrict__ sw, const float* __restrict__ sb,
                                              float* __restrict__ h1){
    int b = blockIdx.y;
    int j = blockIdx.x*8 + (threadIdx.x >> 5);
    int lane = threadIdx.x & 31;
    float4 w = ((const float4*)(sw + (size_t)j*C))[lane];
    float4 f = ((const float4*)(feat + b*C))[lane];
    float s = w.x*f.x + w.y*f.y + w.z*f.z + w.w*f.w;
    #pragma unroll
    for (int off = 16; off > 0; off >>= 1) s += __shfl_xor_sync(0xffffffffu, s, off);
    if (lane == 0) h1[b*DIM + j] = gelu_f(s + sb[j]);
}

__global__ __launch_bounds__(256) void mlp_l2(const float* __restrict__ h1,
                                              const float* __restrict__ w1, const float* __restrict__ b1,
                                              float* __restrict__ h2){
    __shared__ __align__(16) float sh[DIM];
    int b = blockIdx.y, t = threadIdx.x;
    for (int i = t; i < DIM/4; i += 256)
        ((float4*)sh)[i] = ((const float4*)(h1 + b*DIM))[i];
    __syncthreads();
    int j = blockIdx.x*8 + (t >> 5);
    int lane = t & 31;
    const float4* wr = (const float4*)(w1 + (size_t)j*DIM);
    float s = 0.f;
    #pragma unroll
    for (int i = 0; i < 4; i++){
        float4 w = wr[i*32 + lane];
        float4 f = ((const float4*)sh)[i*32 + lane];
        s += w.x*f.x + w.y*f.y + w.z*f.z + w.w*f.w;
    }
    #pragma unroll
    for (int off = 16; off > 0; off >>= 1) s += __shfl_xor_sync(0xffffffffu, s, off);
    if (lane == 0) h2[b*2*DIM + j] = gelu_f(s + b1[j]);
}

__global__ __launch_bounds__(576) void mlp_l3(const float* __restrict__ h2,
                                              const float* __restrict__ w2, const float* __restrict__ b2,
                                              float* __restrict__ lo, float* __restrict__ hi){
    __shared__ __align__(16) float sh[2*DIM];
    int b = blockIdx.x, t = threadIdx.x;
    for (int i = t; i < 2*DIM/4; i += 576)
        ((float4*)sh)[i] = ((const float4*)(h2 + b*2*DIM))[i];
    __syncthreads();
    int j = t >> 5, lane = t & 31;     // 18 warps
    const float4* wr = (const float4*)(w2 + (size_t)j*2*DIM);
    float s = 0.f;
    #pragma unroll
    for (int i = 0; i < 8; i++){
        float4 w = wr[i*32 + lane];
        float4 f = ((const float4*)sh)[i*32 + lane];
        s += w.x*f.x + w.y*f.y + w.z*f.z + w.w*f.w;
    }
    #pragma unroll
    for (int off = 16; off > 0; off >>= 1) s += __shfl_xor_sync(0xffffffffu, s, off);
    if (lane == 0){
        float v = s + b2[j];
        if (j < FL) lo[b*FL + j] = v;
        else        hi[b*FL + (j-FL)] = v;
    }
}

// ---------------- ortho loss (last level only) + energy=0 ----------------
__global__ void ortho_kernel(const float* __restrict__ lo, float* __restrict__ out_scalars){
    int b = threadIdx.x;
    float v[FL]; float ss = 0.f;
    #pragma unroll
    for (int k = 0; k < FL; k++){ v[k] = lo[b*FL+k]; ss += v[k]*v[k]; }
    float den = sqrtf(ss) + 1e-8f;
    float S = 0.f, sq = 0.f;
    #pragma unroll
    for (int k = 0; k < FL; k++){
        float n = v[k]/den;
        S  += fabsf(n);
        sq += n*n;
    }
    float S2  = S*S;
    float amp = fabsf(sq - 1.0f);
    float sm  = fabsf(v[0]);
    #pragma unroll
    for (int k = 1; k < FL; k++) sm += fabsf(v[k]-v[k-1]);
    sm += fabsf(v[FL-1]);
    #pragma unroll
    for (int off = 16; off > 0; off >>= 1){
        S2  += __shfl_xor_sync(0xffffffffu, S2,  off);
        amp += __shfl_xor_sync(0xffffffffu, amp, off);
        sm  += __shfl_xor_sync(0xffffffffu, sm,  off);
    }
    if (b == 0){
        float shift  = 3.0f * S2 / (32.0f*81.0f);
        float ampm   = amp / 32.0f;
        float smm    = sm / (32.0f*10.0f);
        out_scalars[0] = 0.01f*(shift + ampm) + 0.1f*smm;
        out_scalars[1] = 0.0f;
    }
}

// ---------------- per-sample depthwise 9-tap (edge pad) + mean accumulate ----------------
#define DTL 1024
__global__ __launch_bounds__(256) void dw_kernel(
    const float* __restrict__ x, const float* __restrict__ lo, const float* __restrict__ hi,
    float* __restrict__ out_a, float* __restrict__ out_d, float* __restrict__ feat_next)
{
    int row = blockIdx.y;
    int b   = row >> 7;
    int l0  = blockIdx.x * DTL;
    __shared__ __align__(16) float s[DTL + 16];
    __shared__ float wsum[8];
    const float* xr = x + (size_t)row * L;
    int t = threadIdx.x, lane = t & 31, wid = t >> 5;
    {
        const float4* xv = (const float4*)(xr + l0);
        ((float4*)(s + 4))[t] = xv[t];
    }
    if (t < 4){
        int li = l0 - 4 + t;
        s[t] = xr[max(li, 0)];
        int ri = l0 + DTL + t;
        s[DTL + 4 + t] = xr[min(ri, L-1)];
    }
    unsigned long long pf[FL];
    #pragma unroll
    for (int k = 0; k < FL; k++) pf[k] = pack2(__ldg(&lo[b*FL+k]), __ldg(&hi[b*FL+k]));
    __syncthreads();

    int i0 = t * 4;
    float win[12];
    #pragma unroll
    for (int j = 0; j < 12; j++) win[j] = s[i0 + j];
    unsigned long long acc[4];
    #pragma unroll
    for (int p = 0; p < 4; p++) acc[p] = 0ull;
    #pragma unroll
    for (int k = 0; k < FL; k++){
        #pragma unroll
        for (int p = 0; p < 4; p++){
            unsigned long long vv = pack2(win[p+k], win[p+k]);
            acc[p] = fma2(vv, pf[k], acc[p]);
        }
    }
    float4 ra, rd;
    float2 f0 = unpack2(acc[0]), f1 = unpack2(acc[1]), f2 = unpack2(acc[2]), f3 = unpack2(acc[3]);
    ra.x = f0.x; ra.y = f1.x; ra.z = f2.x; ra.w = f3.x;
    rd.x = f0.y; rd.y = f1.y; rd.z = f2.y; rd.w = f3.y;
    size_t idx = (size_t)row*L + l0 + i0;
    *(float4*)(out_a + idx) = ra;
    *(float4*)(out_d + idx) = rd;

    if (feat_next){
        float s4 = (ra.x + ra.y) + (ra.z + ra.w);
        #pragma unroll
        for (int off = 16; off > 0; off >>= 1) s4 += __shfl_xor_sync(0xffffffffu, s4, off);
        if (lane == 0) wsum[wid] = s4;
        __syncthreads();
        if (t == 0){
            float tot = 0.f;
            #pragma unroll
            for (int w = 0; w < 8; w++) tot += wsum[w];
            atomicAdd(feat_next + row, tot * (1.0f/(float)L));
        }
    }
}

// ---------------- weight prep: tf32 fragment-ordered chunks ----------------
// wt2[lvl][ch=tap*8+ch8][co][p], p = ks*8 + c4*2 + h  ->  ci = ch8*16 + ks*8 + c4 + h*4
__global__ void wprep_tf32(const float* __restrict__ gw, uint32_t* __restrict__ wt2){
    int idx = blockIdx.x*256 + threadIdx.x;
    if (idx < 3*24*2048){
        int lvl = idx / (24*2048);
        int r   = idx % (24*2048);
        int ch  = r / 2048;
        int q   = r % 2048;
        int co  = q >> 4;
        int p   = q & 15;
        int ks = p >> 3, rr = p & 7, c4 = rr >> 1, h = rr & 1;
        int tap = ch >> 3;
        int cio = (ch & 7)*16 + ks*8 + c4 + h*4;
        float v = gw[(((size_t)lvl*C + co)*C + cio)*3 + tap];
        uint32_t u;
        asm("cvt.rna.tf32.f32 %0, %1;" : "=r"(u) : "f"(v));
        wt2[idx] = u;
    }
}
__global__ void prep2_kernel(const float* __restrict__ attn2_w, float* __restrict__ w2t,
                             float* __restrict__ feat){
    int idx = blockIdx.x*256 + threadIdx.x;
    if (idx < 2*32*C){
        int lvl = idx / (32*C);
        int r   = idx % (32*C);
        int ci  = r >> 7, co = r & 127;
        w2t[idx] = attn2_w[((size_t)lvl*C + co)*32 + ci];
    }
    if (idx < 2*B*C) feat[B*C + idx] = 0.f;   // zero feat levels 1,2
}

// ---------------- fused gates: tf32 mma conv3 + attn2 (phase1) + attn1 (phase3) ----
// s_x[ci][j] = x[l0 + j - 1], j in [0,130), pitch 136 (conflict-free B-frag LDS)
#define P_X 136
#define SO_WB (C*P_X*4)                 // 69632
#define WCH_B 8192                      // one chunk: [co128][16] u32
#define SO_W2 (SO_WB + 3*WCH_B)        // 94208
#define GSM_ATTN  (SO_W2 + 32*C*4)     // 110592
#define GSM_PLAIN SO_W2                 // 94208

template<bool ATTN, bool A1>
__global__ __launch_bounds__(256, 2) void gatesf_kernel(
    const float* __restrict__ cur, const float* __restrict__ det_raw,
    const uint32_t* __restrict__ wt2, const float* __restrict__ bias,
    const float* __restrict__ a_in, const float* __restrict__ w2t, const float* __restrict__ bias2,
    float* __restrict__ yh_out, float* __restrict__ out,
    const float* __restrict__ w1, const float* __restrict__ b1, float* __restrict__ a_out)
{
    extern __shared__ __align__(16) char smem[];
    float* s_x  = (float*)smem;              // [128][136]
    float* s_w2 = (float*)(smem + SO_W2);    // phase1 weights
    uint32_t wb_base = smem_u32(smem + SO_WB);
    int l0 = blockIdx.x*128, b = blockIdx.y, t = threadIdx.x;
    int wid = t >> 5, lane = t & 31;
    int g = lane >> 2, c4 = lane & 3;
    int co_w = (wid & 3)*32;            // warp co base (m)
    int n0   = (wid >> 2)*64;           // warp l base (n)

    // prologue prefetch chunks 0,1 (independent of fill)
    {
        const char* src = (const char*)wt2;
        cp16(wb_base + t*32,      src + t*32);
        cp16(wb_base + t*32 + 16, src + t*32 + 16);
        cp_commit();
        cp16(wb_base + WCH_B + t*32,      src + WCH_B + t*32);
        cp16(wb_base + WCH_B + t*32 + 16, src + WCH_B + t*32 + 16);
        cp_commit();
    }

    // ---- fill s_x (interior float4 loads, scalar stores; edges j=0/129) ----
    #pragma unroll 4
    for (int k = 0; k < 16; k++){
        int idx4 = t + k*256;
        int ci = idx4 >> 5, j4 = (idx4 & 31)*4;
        float4 v = *(const float4*)(cur + ((size_t)(b*C+ci))*L + l0 + j4);
        float* st = &s_x[ci*P_X + 1 + j4];
        st[0] = v.x; st[1] = v.y; st[2] = v.z; st[3] = v.w;
    }
    {
        int ci = t >> 1;
        size_t row = (size_t)(b*C+ci)*L;
        if ((t & 1) == 0) s_x[ci*P_X]       = (l0 > 0)       ? cur[row + l0 - 1]   : 0.f;
        else              s_x[ci*P_X + 129] = (l0 + 128 < L) ? cur[row + l0 + 128] : 0.f;
    }
    if (ATTN){
        for (int idx = t; idx < 32*C; idx += 256) s_w2[idx] = w2t[idx];
    }
    __syncthreads();

    // ---- phase 1 (ATTN): det' = det*(1+sig(W2*a+b2)) -> yh_out (a from global) ----
    if (ATTN){
        int co0 = wid*16, lq = lane*4;
        unsigned long long acc2[8][4];
        #pragma unroll
        for (int c = 0; c < 8; c++)
            #pragma unroll
            for (int q = 0; q < 4; q++) acc2[c][q] = 0ull;
        #pragma unroll 4
        for (int ci = 0; ci < 32; ci++){
            float4 xv = *(const float4*)(a_in + ((size_t)(b*32+ci))*L + l0 + lq);
            unsigned long long p0 = pack2(xv.x, xv.x);
            unsigned long long p1 = pack2(xv.y, xv.y);
            unsigned long long p2 = pack2(xv.z, xv.z);
            unsigned long long p3 = pack2(xv.w, xv.w);
            const ulonglong2* wp = (const ulonglong2*)(&s_w2[ci*C + co0]);
            unsigned long long wr[8];
            ((ulonglong2*)wr)[0] = wp[0];
            ((ulonglong2*)wr)[1] = wp[1];
            ((ulonglong2*)wr)[2] = wp[2];
            ((ulonglong2*)wr)[3] = wp[3];
            #pragma unroll
            for (int c = 0; c < 8; c++){
                acc2[c][0] = fma2(wr[c], p0, acc2[c][0]);
                acc2[c][1] = fma2(wr[c], p1, acc2[c][1]);
                acc2[c][2] = fma2(wr[c], p2, acc2[c][2]);
                acc2[c][3] = fma2(wr[c], p3, acc2[c][3]);
            }
        }
        #pragma unroll
        for (int c = 0; c < 8; c++){
            int co = co0 + 2*c;
            float2 z[4];
            #pragma unroll
            for (int q = 0; q < 4; q++) z[q] = unpack2(acc2[c][q]);
            #pragma unroll
            for (int s = 0; s < 2; s++){
                float bv = __ldg(&bias2[co+s]);
                size_t idx = ((size_t)(b*C+co+s))*L + l0 + lq;
                float4 dv = *(const float4*)(det_raw + idx);
                dv.x *= 1.0f + sigmoid_f((s ? z[0].y : z[0].x) + bv);
                dv.y *= 1.0f + sigmoid_f((s ? z[1].y : z[1].x) + bv);
                dv.z *= 1.0f + sigmoid_f((s ? z[2].y : z[2].x) + bv);
                dv.w *= 1.0f + sigmoid_f((s ? z[3].y : z[3].x) + bv);
                *(float4*)(yh_out + idx) = dv;
            }
        }
    }

    // ---- phase 2: tf32 mma mainloop (24 chunks: tap = ch>>3, ci16 = (ch&7)*16) ----
    float d[2][8][4];
    #pragma unroll
    for (int mi = 0; mi < 2; mi++)
        #pragma unroll
        for (int ni = 0; ni < 8; ni++)
            #pragma unroll
            for (int r = 0; r < 4; r++) d[mi][ni][r] = 0.f;

    const uint32_t* sx_u = (const uint32_t*)s_x;
    for (int ch = 0; ch < 24; ch++){
        if (ch < 22) cp_wait<1>(); else cp_wait<0>();
        __syncthreads();
        if (ch + 2 < 24){
            uint32_t dst = wb_base + ((ch+2)%3)*WCH_B;
            const char* src = (const char*)wt2 + (size_t)(ch+2)*WCH_B;
            cp16(dst + t*32,      src + t*32);
            cp16(dst + t*32 + 16, src + t*32 + 16);
            cp_commit();
        }
        int tap = ch >> 3;
        int ci_base = (ch & 7)*16;
        const uint32_t* wch = (const uint32_t*)(smem + SO_WB + (ch%3)*WCH_B);
        #pragma unroll
        for (int ks = 0; ks < 2; ks++){
            uint32_t af[2][4];
            #pragma unroll
            for (int mi = 0; mi < 2; mi++){
                int co = co_w + mi*16 + g;
                unsigned long long w0 = *(const unsigned long long*)(wch + co*16     + ks*8 + c4*2);
                unsigned long long w8 = *(const unsigned long long*)(wch + (co+8)*16 + ks*8 + c4*2);
                af[mi][0] = (uint32_t)w0;           // (g,   c)
                af[mi][1] = (uint32_t)w8;           // (g+8, c)
                af[mi][2] = (uint32_t)(w0 >> 32);   // (g,   c+4)
                af[mi][3] = (uint32_t)(w8 >> 32);   // (g+8, c+4)
            }
            int ci = ci_base + ks*8 + c4;
            const uint32_t* xb  = sx_u + ci*P_X + n0 + g + tap;
            const uint32_t* xb4 = xb + 4*P_X;
            #pragma unroll
            for (int ni = 0; ni < 8; ni++){
                uint32_t b0v = xb[ni*8];
                uint32_t b1v = xb4[ni*8];
                mma_tf32(d[0][ni], af[0][0], af[0][1], af[0][2], af[0][3], b0v, b1v);
                mma_tf32(d[1][ni], af[1][0], af[1][1], af[1][2], af[1][3], b0v, b1v);
            }
        }
    }
    __syncthreads();     // all B reads done; s_x region becomes s_d

    // ---- stage D -> s_d[co][l] (pitch 136) ----
    float* s_d = s_x;
    #pragma unroll
    for (int mi = 0; mi < 2; mi++){
        int co = co_w + mi*16 + g;
        #pragma unroll
        for (int ni = 0; ni < 8; ni++){
            int l = n0 + ni*8 + c4*2;
            *(float2*)&s_d[co*P_X + l]     = make_float2(d[mi][ni][0], d[mi][ni][1]);
            *(float2*)&s_d[(co+8)*P_X + l] = make_float2(d[mi][ni][2], d[mi][ni][3]);
        }
    }
    __syncthreads();

    // ---- final pass: out = cur + sig(z+bias)*det' (cur/det from global, L2-hot) ----
    #pragma unroll 4
    for (int k = 0; k < 16; k++){
        int idx4 = t + k*256;
        int co = idx4 >> 5, l4 = (idx4 & 31)*4;
        float4 z4 = *(const float4*)&s_d[co*P_X + l4];
        float bv = __ldg(&bias[co]);
        size_t gix = ((size_t)(b*C+co))*L + l0 + l4;
        float4 cv = *(const float4*)(cur + gix);
        const float* dsrc = ATTN ? yh_out : det_raw;
        float4 dv = *(const float4*)(dsrc + gix);
        float4 ov;
        ov.x = cv.x + sigmoid_f(z4.x + bv)*dv.x;
        ov.y = cv.y + sigmoid_f(z4.y + bv)*dv.y;
        ov.z = cv.z + sigmoid_f(z4.z + bv)*dv.z;
        ov.w = cv.w + sigmoid_f(z4.w + bv)*dv.w;
        *(float4*)(out + gix) = ov;
        if (A1) *(float4*)&s_d[co*P_X + l4] = ov;
    }

    // ---- phase 3 (A1): a_out = gelu(W1*out + b1) ----
    if (A1){
        __syncthreads();
        float* s_w1 = (float*)(smem + SO_WB);   // wbuf drained
        for (int idx = t; idx < 32*C; idx += 256){
            int ci = idx >> 5, c2 = idx & 31;
            s_w1[idx] = w1[c2*C + ci];
        }
        __syncthreads();
        int c2b = wid*4;
        unsigned long long acc3[2][4];
        #pragma unroll
        for (int pc = 0; pc < 2; pc++)
            #pragma unroll
            for (int q = 0; q < 4; q++) acc3[pc][q] = 0ull;
        #pragma unroll 4
        for (int ci = 0; ci < C; ci++){
            ulonglong2 wv = *(const ulonglong2*)(&s_w1[ci*32 + c2b]);
            #pragma unroll
            for (int q = 0; q < 4; q++){
                float xv = s_d[ci*P_X + lane + 32*q];
                unsigned long long p = pack2(xv, xv);
                acc3[0][q] = fma2(wv.x, p, acc3[0][q]);
                acc3[1][q] = fma2(wv.y, p, acc3[1][q]);
            }
        }
        #pragma unroll
        for (int pc = 0; pc < 2; pc++){
            int c2 = c2b + 2*pc;
            float b10 = __ldg(&b1[c2]);
            float b11 = __ldg(&b1[c2+1]);
            #pragma unroll
            for (int q = 0; q < 4; q++){
                float2 z = unpack2(acc3[pc][q]);
                size_t ix = ((size_t)(b*32 + c2))*L + l0 + lane + 32*q;
                a_out[ix]     = gelu_f(z.x + b10);
                a_out[ix + L] = gelu_f(z.y + b11);
            }
        }
    }
}

// ---------------- host launch ----------------
extern "C" void kernel_launch(void* const* d_in, const int* in_sizes, int n_in,
                              void* d_out, int out_size)
{
    const float* x       = (const float*)d_in[0];
    const float* stat_w  = (const float*)d_in[1];
    const float* stat_b  = (const float*)d_in[2];
    const float* wg1_w   = (const float*)d_in[3];
    const float* wg1_b   = (const float*)d_in[4];
    const float* wg2_w   = (const float*)d_in[5];
    const float* wg2_b   = (const float*)d_in[6];
    const float* gates_w = (const float*)d_in[7];
    const float* gates_b = (const float*)d_in[8];
    const float* attn1_w = (const float*)d_in[9];
    const float* attn1_b = (const float*)d_in[10];
    const float* attn2_w = (const float*)d_in[11];
    const float* attn2_b = (const float*)d_in[12];
    float* out = (float*)d_out;

    float *a1, *a2, *a3, *attn, *feat, *h1, *h2, *w2t;
    uint32_t *wt2;
    cudaGetSymbolAddress((void**)&a1,   g_a1);
    cudaGetSymbolAddress((void**)&a2,   g_a2);
    cudaGetSymbolAddress((void**)&a3,   g_a3);
    cudaGetSymbolAddress((void**)&attn, g_attn);
    cudaGetSymbolAddress((void**)&feat, g_feat);
    cudaGetSymbolAddress((void**)&h1,   g_h1);
    cudaGetSymbolAddress((void**)&h2,   g_h2);
    cudaGetSymbolAddress((void**)&wt2,  g_wt2);
    cudaGetSymbolAddress((void**)&w2t,  g_w2t);

    float* yl  = out;
    float* yh0 = out + NYL;
    float* yh1 = out + 2*NYL;
    float* yh2 = out + 3*NYL;
    float* scal= out + 4*NYL;
    float* lo_all = out + 4*NYL + 2;
    float* hi_all = lo_all + 3*B*FL;

    cudaFuncSetAttribute((const void*)gatesf_kernel<false,true>,  cudaFuncAttributeMaxDynamicSharedMemorySize, GSM_PLAIN);
    cudaFuncSetAttribute((const void*)gatesf_kernel<true,true>,   cudaFuncAttributeMaxDynamicSharedMemorySize, GSM_ATTN);
    cudaFuncSetAttribute((const void*)gatesf_kernel<true,false>,  cudaFuncAttributeMaxDynamicSharedMemorySize, GSM_ATTN);

    wprep_tf32<<<(3*24*2048 + 255)/256, 256>>>(gates_w, wt2);
    prep2_kernel<<<(2*32*C + 255)/256, 256>>>(attn2_w, w2t, feat);

    const float* ain[3]  = {x, a1, a2};
    float*       aout[3] = {a1, a2, a3};
    float*       dets[3] = {yh0, yh1, yh2};

    mean_kernel<<<NROW, 256>>>(x, feat);
    for (int lvl = 0; lvl < 3; lvl++){
        float* lo = lo_all + lvl*B*FL;
        float* hi = hi_all + lvl*B*FL;
        const float* f = feat + lvl*B*C;
        mlp_l1<<<dim3(DIM/8, B), 256>>>(f, stat_w, stat_b, h1);
        mlp_l2<<<dim3(2*DIM/8, B), 256>>>(h1, wg1_w, wg1_b, h2);
        mlp_l3<<<B, 576>>>(h2, wg2_w, wg2_b, lo, hi);
        float* fnext = (lvl < 2) ? (feat + (lvl+1)*B*C) : nullptr;
        dw_kernel<<<dim3(L/DTL, NROW), 256>>>(ain[lvl], lo, hi, aout[lvl], dets[lvl], fnext);
    }

    ortho_kernel<<<1, 32>>>(lo_all + 2*B*FL, scal);

    // i = 2: gates (no attn2) + fused attn1 for level 1 -> attn
    gatesf_kernel<false,true><<<dim3(L/128, B), 256, GSM_PLAIN>>>(
        a3, yh2, wt2 + 2*24*2048, gates_b + 2*C,
        nullptr, nullptr, nullptr, nullptr, a1,
        attn1_w + 1*(C/4)*C, attn1_b + (C/4), attn);
    // i = 1: gates + attn2(level 1) + fused attn1 for level 0 -> attn
    gatesf_kernel<true,true><<<dim3(L/128, B), 256, GSM_ATTN>>>(
        a1, yh1, wt2 + 1*24*2048, gates_b + 1*C,
        attn, w2t + 32*C, attn2_b + C, yh1, a2,
        attn1_w, attn1_b, attn);
    // i = 0: gates + attn2(level 0) -> yl
    gatesf_kernel<true,false><<<dim3(L/128, B), 256, GSM_ATTN>>>(
        a2, yh0, wt2, gates_b,
        attn, w2t, attn2_b, yh0, yl,
        nullptr, nullptr, nullptr);
}

// round 15
// speedup vs baseline: 2.2118x; 1.4073x over previous
#include <cuda_runtime.h>
#include <math.h>
#include <stdint.h>

#define B 32
#define C 128
#define L 4096
#define NROW (B*C)
#define BCL (B*C*L)            // 16777216
#define FL 9
#define DIM 512
#define NYL ((size_t)BCL)

// ---------------- scratch (device globals; no allocation) ----------------
__device__ float g_a1[BCL];
__device__ float g_a2[BCL];
__device__ float g_a3[BCL];
__device__ float g_attn[B*(C/4)*L];
__device__ float g_feat[3*B*C];          // per-level feature means
__device__ float g_h1[B*DIM];
__device__ float g_h2[B*2*DIM];
__device__ __align__(16) uint32_t g_wt2[3*24*2048];  // tf32 gates weights [lvl][tap*8+ch][co][16]
__device__ float g_w2t[2*32*C];          // attn2 weights [lvl][ci][co]

__device__ __forceinline__ float gelu_f(float x){
    return 0.5f*x*(1.0f+erff(x*0.7071067811865476f));
}
__device__ __forceinline__ float sigmoid_f(float x){
    return 1.0f/(1.0f+expf(-x));
}

// ---- packed f32x2 helpers (Blackwell FFMA2) ----
__device__ __forceinline__ unsigned long long pack2(float lo, float hi){
    unsigned long long r;
    asm("mov.b64 %0, {%1, %2};" : "=l"(r) : "f"(lo), "f"(hi));
    return r;
}
__device__ __forceinline__ unsigned long long fma2(unsigned long long a, unsigned long long b, unsigned long long c){
    unsigned long long d;
    asm("fma.rn.f32x2 %0, %1, %2, %3;" : "=l"(d) : "l"(a), "l"(b), "l"(c));
    return d;
}
__device__ __forceinline__ float2 unpack2(unsigned long long v){
    float2 f;
    asm("mov.b64 {%0, %1}, %2;" : "=f"(f.x), "=f"(f.y) : "l"(v));
    return f;
}

// ---- cp.async + mma helpers (baseline PTX) ----
__device__ __forceinline__ uint32_t smem_u32(const void* p){
    uint32_t a;
    asm("{ .reg .u64 t; cvta.to.shared.u64 t, %1; cvt.u32.u64 %0, t; }" : "=r"(a) : "l"(p));
    return a;
}
__device__ __forceinline__ void cp16(uint32_t dst, const void* src){
    asm volatile("cp.async.ca.shared.global [%0], [%1], 16;" :: "r"(dst), "l"(src) : "memory");
}
__device__ __forceinline__ void cp_commit(){
    asm volatile("cp.async.commit_group;" ::: "memory");
}
template<int N>
__device__ __forceinline__ void cp_wait(){
    asm volatile("cp.async.wait_group %0;" :: "n"(N) : "memory");
}
__device__ __forceinline__ void mma_tf32(float* d, uint32_t a0, uint32_t a1, uint32_t a2, uint32_t a3,
                                         uint32_t b0, uint32_t b1){
    asm volatile("mma.sync.aligned.m16n8k8.row.col.f32.tf32.tf32.f32 "
        "{%0,%1,%2,%3}, {%4,%5,%6,%7}, {%8,%9}, {%0,%1,%2,%3};"
        : "+f"(d[0]), "+f"(d[1]), "+f"(d[2]), "+f"(d[3])
        : "r"(a0), "r"(a1), "r"(a2), "r"(a3), "r"(b0), "r"(b1));
}

// ---------------- mean over L (level 0 only) ----------------
__global__ __launch_bounds__(256) void mean_kernel(const float* __restrict__ x,
                                                   float* __restrict__ feat){
    int row = blockIdx.x;
    const float4* p = (const float4*)(x + (size_t)row*L);
    float s = 0.f;
    for (int i = threadIdx.x; i < L/4; i += 256){
        float4 v = p[i];
        s += (v.x+v.y)+(v.z+v.w);
    }
    __shared__ float red[256];
    red[threadIdx.x] = s; __syncthreads();
    for (int off = 128; off > 0; off >>= 1){
        if (threadIdx.x < off) red[threadIdx.x] += red[threadIdx.x+off];
        __syncthreads();
    }
    if (threadIdx.x == 0) feat[row] = red[0] * (1.0f/(float)L);
}

// ---------------- MLP layers (warp-per-output GEMV) ----------------
__global__ __launch_bounds__(256) void mlp_l1(const float* __restrict__ feat,
                                              const float* __restrict__ sw, const float* __restrict__ sb,
                                              float* __restrict__ h1){
    int b = blockIdx.y;
    int j = blockIdx.x*8 + (threadIdx.x >> 5);
    int lane = threadIdx.x & 31;
    float4 w = ((const float4*)(sw + (size_t)j*C))[lane];
    float4 f = ((const float4*)(feat + b*C))[lane];
    float s = w.x*f.x + w.y*f.y + w.z*f.z + w.w*f.w;
    #pragma unroll
    for (int off = 16; off > 0; off >>= 1) s += __shfl_xor_sync(0xffffffffu, s, off);
    if (lane == 0) h1[b*DIM + j] = gelu_f(s + sb[j]);
}

__global__ __launch_bounds__(256) void mlp_l2(const float* __restrict__ h1,
                                              const float* __restrict__ w1, const float* __restrict__ b1,
                                              float* __restrict__ h2){
    __shared__ __align__(16) float sh[DIM];
    int b = blockIdx.y, t = threadIdx.x;
    for (int i = t; i < DIM/4; i += 256)
        ((float4*)sh)[i] = ((const float4*)(h1 + b*DIM))[i];
    __syncthreads();
    int j = blockIdx.x*8 + (t >> 5);
    int lane = t & 31;
    const float4* wr = (const float4*)(w1 + (size_t)j*DIM);
    float s = 0.f;
    #pragma unroll
    for (int i = 0; i < 4; i++){
        float4 w = wr[i*32 + lane];
        float4 f = ((const float4*)sh)[i*32 + lane];
        s += w.x*f.x + w.y*f.y + w.z*f.z + w.w*f.w;
    }
    #pragma unroll
    for (int off = 16; off > 0; off >>= 1) s += __shfl_xor_sync(0xffffffffu, s, off);
    if (lane == 0) h2[b*2*DIM + j] = gelu_f(s + b1[j]);
}

__global__ __launch_bounds__(576) void mlp_l3(const float* __restrict__ h2,
                                              const float* __restrict__ w2, const float* __restrict__ b2,
                                              float* __restrict__ lo, float* __restrict__ hi){
    __shared__ __align__(16) float sh[2*DIM];
    int b = blockIdx.x, t = threadIdx.x;
    for (int i = t; i < 2*DIM/4; i += 576)
        ((float4*)sh)[i] = ((const float4*)(h2 + b*2*DIM))[i];
    __syncthreads();
    int j = t >> 5, lane = t & 31;     // 18 warps
    const float4* wr = (const float4*)(w2 + (size_t)j*2*DIM);
    float s = 0.f;
    #pragma unroll
    for (int i = 0; i < 8; i++){
        float4 w = wr[i*32 + lane];
        float4 f = ((const float4*)sh)[i*32 + lane];
        s += w.x*f.x + w.y*f.y + w.z*f.z + w.w*f.w;
    }
    #pragma unroll
    for (int off = 16; off > 0; off >>= 1) s += __shfl_xor_sync(0xffffffffu, s, off);
    if (lane == 0){
        float v = s + b2[j];
        if (j < FL) lo[b*FL + j] = v;
        else        hi[b*FL + (j-FL)] = v;
    }
}

// ---------------- ortho loss (last level only) + energy=0 ----------------
__global__ void ortho_kernel(const float* __restrict__ lo, float* __restrict__ out_scalars){
    int b = threadIdx.x;
    float v[FL]; float ss = 0.f;
    #pragma unroll
    for (int k = 0; k < FL; k++){ v[k] = lo[b*FL+k]; ss += v[k]*v[k]; }
    float den = sqrtf(ss) + 1e-8f;
    float S = 0.f, sq = 0.f;
    #pragma unroll
    for (int k = 0; k < FL; k++){
        float n = v[k]/den;
        S  += fabsf(n);
        sq += n*n;
    }
    float S2  = S*S;
    float amp = fabsf(sq - 1.0f);
    float sm  = fabsf(v[0]);
    #pragma unroll
    for (int k = 1; k < FL; k++) sm += fabsf(v[k]-v[k-1]);
    sm += fabsf(v[FL-1]);
    #pragma unroll
    for (int off = 16; off > 0; off >>= 1){
        S2  += __shfl_xor_sync(0xffffffffu, S2,  off);
        amp += __shfl_xor_sync(0xffffffffu, amp, off);
        sm  += __shfl_xor_sync(0xffffffffu, sm,  off);
    }
    if (b == 0){
        float shift  = 3.0f * S2 / (32.0f*81.0f);
        float ampm   = amp / 32.0f;
        float smm    = sm / (32.0f*10.0f);
        out_scalars[0] = 0.01f*(shift + ampm) + 0.1f*smm;
        out_scalars[1] = 0.0f;
    }
}

// ---------------- per-sample depthwise 9-tap (edge pad) + mean accumulate ----------------
#define DTL 1024
__global__ __launch_bounds__(256) void dw_kernel(
    const float* __restrict__ x, const float* __restrict__ lo, const float* __restrict__ hi,
    float* __restrict__ out_a, float* __restrict__ out_d, float* __restrict__ feat_next)
{
    int row = blockIdx.y;
    int b   = row >> 7;
    int l0  = blockIdx.x * DTL;
    __shared__ __align__(16) float s[DTL + 16];
    __shared__ float wsum[8];
    const float* xr = x + (size_t)row * L;
    int t = threadIdx.x, lane = t & 31, wid = t >> 5;
    {
        const float4* xv = (const float4*)(xr + l0);
        ((float4*)(s + 4))[t] = xv[t];
    }
    if (t < 4){
        int li = l0 - 4 + t;
        s[t] = xr[max(li, 0)];
        int ri = l0 + DTL + t;
        s[DTL + 4 + t] = xr[min(ri, L-1)];
    }
    unsigned long long pf[FL];
    #pragma unroll
    for (int k = 0; k < FL; k++) pf[k] = pack2(__ldg(&lo[b*FL+k]), __ldg(&hi[b*FL+k]));
    __syncthreads();

    int i0 = t * 4;
    float win[12];
    #pragma unroll
    for (int j = 0; j < 12; j++) win[j] = s[i0 + j];
    unsigned long long acc[4];
    #pragma unroll
    for (int p = 0; p < 4; p++) acc[p] = 0ull;
    #pragma unroll
    for (int k = 0; k < FL; k++){
        #pragma unroll
        for (int p = 0; p < 4; p++){
            unsigned long long vv = pack2(win[p+k], win[p+k]);
            acc[p] = fma2(vv, pf[k], acc[p]);
        }
    }
    float4 ra, rd;
    float2 f0 = unpack2(acc[0]), f1 = unpack2(acc[1]), f2 = unpack2(acc[2]), f3 = unpack2(acc[3]);
    ra.x = f0.x; ra.y = f1.x; ra.z = f2.x; ra.w = f3.x;
    rd.x = f0.y; rd.y = f1.y; rd.z = f2.y; rd.w = f3.y;
    size_t idx = (size_t)row*L + l0 + i0;
    *(float4*)(out_a + idx) = ra;
    *(float4*)(out_d + idx) = rd;

    if (feat_next){
        float s4 = (ra.x + ra.y) + (ra.z + ra.w);
        #pragma unroll
        for (int off = 16; off > 0; off >>= 1) s4 += __shfl_xor_sync(0xffffffffu, s4, off);
        if (lane == 0) wsum[wid] = s4;
        __syncthreads();
        if (t == 0){
            float tot = 0.f;
            #pragma unroll
            for (int w = 0; w < 8; w++) tot += wsum[w];
            atomicAdd(feat_next + row, tot * (1.0f/(float)L));
        }
    }
}

// ---------------- weight prep: tf32 fragment-ordered chunks ----------------
// wt2[lvl][ch=tap*8+ch8][co][p], p = ks*8 + c4*2 + h  ->  ci = ch8*16 + ks*8 + c4 + h*4
__global__ void wprep_tf32(const float* __restrict__ gw, uint32_t* __restrict__ wt2){
    int idx = blockIdx.x*256 + threadIdx.x;
    if (idx < 3*24*2048){
        int lvl = idx / (24*2048);
        int r   = idx % (24*2048);
        int ch  = r / 2048;
        int q   = r % 2048;
        int co  = q >> 4;
        int p   = q & 15;
        int ks = p >> 3, rr = p & 7, c4 = rr >> 1, h = rr & 1;
        int tap = ch >> 3;
        int cio = (ch & 7)*16 + ks*8 + c4 + h*4;
        float v = gw[(((size_t)lvl*C + co)*C + cio)*3 + tap];
        uint32_t u;
        asm("cvt.rna.tf32.f32 %0, %1;" : "=r"(u) : "f"(v));
        wt2[idx] = u;
    }
}
__global__ void prep2_kernel(const float* __restrict__ attn2_w, float* __restrict__ w2t,
                             float* __restrict__ feat){
    int idx = blockIdx.x*256 + threadIdx.x;
    if (idx < 2*32*C){
        int lvl = idx / (32*C);
        int r   = idx % (32*C);
        int ci  = r >> 7, co = r & 127;
        w2t[idx] = attn2_w[((size_t)lvl*C + co)*32 + ci];
    }
    if (idx < 2*B*C) feat[B*C + idx] = 0.f;   // zero feat levels 1,2
}

// ---------------- fused gates: tf32 mma conv3 + attn2 (phase1, split) + attn1 (phase3) ----
// s_x[ci][j] = x[l0 + j - 1], j in [0,130), pitch 136 (conflict-free B-frag LDS)
#define P_X 136
#define SO_WB (C*P_X*4)                 // 69632
#define WCH_B 8192                      // one chunk: [co128][16] u32
#define SO_W2 (SO_WB + 3*WCH_B)        // 94208
#define GSM_ATTN  (SO_W2 + 32*C*4)     // 110592
#define GSM_PLAIN SO_W2                 // 94208

template<bool ATTN, bool A1>
__global__ __launch_bounds__(256, 2) void gatesf_kernel(
    const float* __restrict__ cur, const float* __restrict__ det_raw,
    const uint32_t* __restrict__ wt2, const float* __restrict__ bias,
    const float* __restrict__ a_in, const float* __restrict__ w2t, const float* __restrict__ bias2,
    float* __restrict__ yh_out, float* __restrict__ out,
    const float* __restrict__ w1, const float* __restrict__ b1, float* __restrict__ a_out)
{
    extern __shared__ __align__(16) char smem[];
    float* s_x  = (float*)smem;              // [128][136]
    float* s_w2 = (float*)(smem + SO_W2);    // phase1 weights
    uint32_t wb_base = smem_u32(smem + SO_WB);
    int l0 = blockIdx.x*128, b = blockIdx.y, t = threadIdx.x;
    int wid = t >> 5, lane = t & 31;
    int g = lane >> 2, c4 = lane & 3;
    int co_w = (wid & 3)*32;            // warp co base (m)
    int n0   = (wid >> 2)*64;           // warp l base (n)

    // prologue prefetch chunks 0,1 (independent of fill)
    {
        const char* src = (const char*)wt2;
        cp16(wb_base + t*32,      src + t*32);
        cp16(wb_base + t*32 + 16, src + t*32 + 16);
        cp_commit();
        cp16(wb_base + WCH_B + t*32,      src + WCH_B + t*32);
        cp16(wb_base + WCH_B + t*32 + 16, src + WCH_B + t*32 + 16);
        cp_commit();
    }

    // ---- fill s_x (interior float4 loads, scalar stores; edges j=0/129) ----
    #pragma unroll 4
    for (int k = 0; k < 16; k++){
        int idx4 = t + k*256;
        int ci = idx4 >> 5, j4 = (idx4 & 31)*4;
        float4 v = *(const float4*)(cur + ((size_t)(b*C+ci))*L + l0 + j4);
        float* st = &s_x[ci*P_X + 1 + j4];
        st[0] = v.x; st[1] = v.y; st[2] = v.z; st[3] = v.w;
    }
    {
        int ci = t >> 1;
        size_t row = (size_t)(b*C+ci)*L;
        if ((t & 1) == 0) s_x[ci*P_X]       = (l0 > 0)       ? cur[row + l0 - 1]   : 0.f;
        else              s_x[ci*P_X + 129] = (l0 + 128 < L) ? cur[row + l0 + 128] : 0.f;
    }
    if (ATTN){
        for (int idx = t; idx < 32*C; idx += 256) s_w2[idx] = w2t[idx];
    }
    __syncthreads();

    // ---- phase 1 (ATTN): det' = det*(1+sig(W2*a+b2)) -> yh_out, in 2 half-passes ----
    if (ATTN){
        int co0 = wid*16, lq = lane*4;
        #pragma unroll 1
        for (int half = 0; half < 2; half++){
            unsigned long long acc2[4][4];
            #pragma unroll
            for (int c = 0; c < 4; c++)
                #pragma unroll
                for (int q = 0; q < 4; q++) acc2[c][q] = 0ull;
            #pragma unroll 4
            for (int ci = 0; ci < 32; ci++){
                float4 xv = *(const float4*)(a_in + ((size_t)(b*32+ci))*L + l0 + lq);
                unsigned long long p0 = pack2(xv.x, xv.x);
                unsigned long long p1 = pack2(xv.y, xv.y);
                unsigned long long p2 = pack2(xv.z, xv.z);
                unsigned long long p3 = pack2(xv.w, xv.w);
                const ulonglong2* wp = (const ulonglong2*)(&s_w2[ci*C + co0 + half*8]);
                unsigned long long wr[4];
                ((ulonglong2*)wr)[0] = wp[0];
                ((ulonglong2*)wr)[1] = wp[1];
                #pragma unroll
                for (int c = 0; c < 4; c++){
                    acc2[c][0] = fma2(wr[c], p0, acc2[c][0]);
                    acc2[c][1] = fma2(wr[c], p1, acc2[c][1]);
                    acc2[c][2] = fma2(wr[c], p2, acc2[c][2]);
                    acc2[c][3] = fma2(wr[c], p3, acc2[c][3]);
                }
            }
            #pragma unroll
            for (int c = 0; c < 4; c++){
                int co = co0 + half*8 + 2*c;
                float2 z[4];
                #pragma unroll
                for (int q = 0; q < 4; q++) z[q] = unpack2(acc2[c][q]);
                #pragma unroll
                for (int s = 0; s < 2; s++){
                    float bv = __ldg(&bias2[co+s]);
                    size_t idx = ((size_t)(b*C+co+s))*L + l0 + lq;
                    float4 dv = *(const float4*)(det_raw + idx);
                    dv.x *= 1.0f + sigmoid_f((s ? z[0].y : z[0].x) + bv);
                    dv.y *= 1.0f + sigmoid_f((s ? z[1].y : z[1].x) + bv);
                    dv.z *= 1.0f + sigmoid_f((s ? z[2].y : z[2].x) + bv);
                    dv.w *= 1.0f + sigmoid_f((s ? z[3].y : z[3].x) + bv);
                    *(float4*)(yh_out + idx) = dv;
                }
            }
        }
    }

    // ---- phase 2: tf32 mma mainloop (24 chunks: tap = ch>>3, ci16 = (ch&7)*16) ----
    float d[2][8][4];
    #pragma unroll
    for (int mi = 0; mi < 2; mi++)
        #pragma unroll
        for (int ni = 0; ni < 8; ni++)
            #pragma unroll
            for (int r = 0; r < 4; r++) d[mi][ni][r] = 0.f;

    const uint32_t* sx_u = (const uint32_t*)s_x;
    for (int ch = 0; ch < 24; ch++){
        if (ch < 22) cp_wait<1>(); else cp_wait<0>();
        __syncthreads();
        if (ch + 2 < 24){
            uint32_t dst = wb_base + ((ch+2)%3)*WCH_B;
            const char* src = (const char*)wt2 + (size_t)(ch+2)*WCH_B;
            cp16(dst + t*32,      src + t*32);
            cp16(dst + t*32 + 16, src + t*32 + 16);
            cp_commit();
        }
        int tap = ch >> 3;
        int ci_base = (ch & 7)*16;
        const uint32_t* wch = (const uint32_t*)(smem + SO_WB + (ch%3)*WCH_B);
        #pragma unroll
        for (int ks = 0; ks < 2; ks++){
            uint32_t af[2][4];
            #pragma unroll
            for (int mi = 0; mi < 2; mi++){
                int co = co_w + mi*16 + g;
                unsigned long long w0 = *(const unsigned long long*)(wch + co*16     + ks*8 + c4*2);
                unsigned long long w8 = *(const unsigned long long*)(wch + (co+8)*16 + ks*8 + c4*2);
                af[mi][0] = (uint32_t)w0;           // (g,   c)
                af[mi][1] = (uint32_t)w8;           // (g+8, c)
                af[mi][2] = (uint32_t)(w0 >> 32);   // (g,   c+4)
                af[mi][3] = (uint32_t)(w8 >> 32);   // (g+8, c+4)
            }
            int ci = ci_base + ks*8 + c4;
            const uint32_t* xb  = sx_u + ci*P_X + n0 + g + tap;
            const uint32_t* xb4 = xb + 4*P_X;
            #pragma unroll
            for (int ni = 0; ni < 8; ni++){
                uint32_t b0v = xb[ni*8];
                uint32_t b1v = xb4[ni*8];
                mma_tf32(d[0][ni], af[0][0], af[0][1], af[0][2], af[0][3], b0v, b1v);
                mma_tf32(d[1][ni], af[1][0], af[1][1], af[1][2], af[1][3], b0v, b1v);
            }
        }
    }
    __syncthreads();     // all B-frag reads done before epilogue overwrites s_x (A1)

    // ---- epilogue: out = cur(s_x) + sig(z+bias)*det'  (direct from frags) ----
    {
        const float* dsrc = ATTN ? yh_out : det_raw;
        #pragma unroll
        for (int mi = 0; mi < 2; mi++){
            #pragma unroll
            for (int half = 0; half < 2; half++){
                int co = co_w + mi*16 + g + half*8;
                float bv = __ldg(&bias[co]);
                size_t rowg = ((size_t)(b*C+co))*L + l0;
                #pragma unroll
                for (int ni = 0; ni < 8; ni++){
                    int l = n0 + ni*8 + c4*2;
                    float z0 = d[mi][ni][half*2 + 0];
                    float z1 = d[mi][ni][half*2 + 1];
                    float c0 = s_x[co*P_X + l + 1];
                    float c1 = s_x[co*P_X + l + 2];
                    float2 dv = *(const float2*)(dsrc + rowg + l);
                    float o0 = c0 + sigmoid_f(z0 + bv)*dv.x;
                    float o1 = c1 + sigmoid_f(z1 + bv)*dv.y;
                    *(float2*)(out + rowg + l) = make_float2(o0, o1);
                    if (A1){
                        s_x[co*P_X + l + 1] = o0;
                        s_x[co*P_X + l + 2] = o1;
                    }
                }
            }
        }
    }

    // ---- phase 3 (A1): a_out = gelu(W1*out + b1), out read from s_x (+1 offset) ----
    if (A1){
        __syncthreads();
        float* s_w1 = (float*)(smem + SO_WB);   // wbuf drained
        for (int idx = t; idx < 32*C; idx += 256){
            int ci = idx >> 5, c2 = idx & 31;
            s_w1[idx] = w1[c2*C + ci];
        }
        __syncthreads();
        int c2b = wid*4;
        unsigned long long acc3[2][4];
        #pragma unroll
        for (int pc = 0; pc < 2; pc++)
            #pragma unroll
            for (int q = 0; q < 4; q++) acc3[pc][q] = 0ull;
        #pragma unroll 4
        for (int ci = 0; ci < C; ci++){
            ulonglong2 wv = *(const ulonglong2*)(&s_w1[ci*32 + c2b]);
            #pragma unroll
            for (int q = 0; q < 4; q++){
                float xv = s_x[ci*P_X + 1 + lane + 32*q];
                unsigned long long p = pack2(xv, xv);
                acc3[0][q] = fma2(wv.x, p, acc3[0][q]);
                acc3[1][q] = fma2(wv.y, p, acc3[1][q]);
            }
        }
        #pragma unroll
        for (int pc = 0; pc < 2; pc++){
            int c2 = c2b + 2*pc;
            float b10 = __ldg(&b1[c2]);
            float b11 = __ldg(&b1[c2+1]);
            #pragma unroll
            for (int q = 0; q < 4; q++){
                float2 z = unpack2(acc3[pc][q]);
                size_t ix = ((size_t)(b*32 + c2))*L + l0 + lane + 32*q;
                a_out[ix]     = gelu_f(z.x + b10);
                a_out[ix + L] = gelu_f(z.y + b11);
            }
        }
    }
}

// ---------------- host launch ----------------
extern "C" void kernel_launch(void* const* d_in, const int* in_sizes, int n_in,
                              void* d_out, int out_size)
{
    const float* x       = (const float*)d_in[0];
    const float* stat_w  = (const float*)d_in[1];
    const float* stat_b  = (const float*)d_in[2];
    const float* wg1_w   = (const float*)d_in[3];
    const float* wg1_b   = (const float*)d_in[4];
    const float* wg2_w   = (const float*)d_in[5];
    const float* wg2_b   = (const float*)d_in[6];
    const float* gates_w = (const float*)d_in[7];
    const float* gates_b = (const float*)d_in[8];
    const float* attn1_w = (const float*)d_in[9];
    const float* attn1_b = (const float*)d_in[10];
    const float* attn2_w = (const float*)d_in[11];
    const float* attn2_b = (const float*)d_in[12];
    float* out = (float*)d_out;

    float *a1, *a2, *a3, *attn, *feat, *h1, *h2, *w2t;
    uint32_t *wt2;
    cudaGetSymbolAddress((void**)&a1,   g_a1);
    cudaGetSymbolAddress((void**)&a2,   g_a2);
    cudaGetSymbolAddress((void**)&a3,   g_a3);
    cudaGetSymbolAddress((void**)&attn, g_attn);
    cudaGetSymbolAddress((void**)&feat, g_feat);
    cudaGetSymbolAddress((void**)&h1,   g_h1);
    cudaGetSymbolAddress((void**)&h2,   g_h2);
    cudaGetSymbolAddress((void**)&wt2,  g_wt2);
    cudaGetSymbolAddress((void**)&w2t,  g_w2t);

    float* yl  = out;
    float* yh0 = out + NYL;
    float* yh1 = out + 2*NYL;
    float* yh2 = out + 3*NYL;
    float* scal= out + 4*NYL;
    float* lo_all = out + 4*NYL + 2;
    float* hi_all = lo_all + 3*B*FL;

    cudaFuncSetAttribute((const void*)gatesf_kernel<false,true>,  cudaFuncAttributeMaxDynamicSharedMemorySize, GSM_PLAIN);
    cudaFuncSetAttribute((const void*)gatesf_kernel<true,true>,   cudaFuncAttributeMaxDynamicSharedMemorySize, GSM_ATTN);
    cudaFuncSetAttribute((const void*)gatesf_kernel<true,false>,  cudaFuncAttributeMaxDynamicSharedMemorySize, GSM_ATTN);

    wprep_tf32<<<(3*24*2048 + 255)/256, 256>>>(gates_w, wt2);
    prep2_kernel<<<(2*32*C + 255)/256, 256>>>(attn2_w, w2t, feat);

    const float* ain[3]  = {x, a1, a2};
    float*       aout[3] = {a1, a2, a3};
    float*       dets[3] = {yh0, yh1, yh2};

    mean_kernel<<<NROW, 256>>>(x, feat);
    for (int lvl = 0; lvl < 3; lvl++){
        float* lo = lo_all + lvl*B*FL;
        float* hi = hi_all + lvl*B*FL;
        const float* f = feat + lvl*B*C;
        mlp_l1<<<dim3(DIM/8, B), 256>>>(f, stat_w, stat_b, h1);
        mlp_l2<<<dim3(2*DIM/8, B), 256>>>(h1, wg1_w, wg1_b, h2);
        mlp_l3<<<B, 576>>>(h2, wg2_w, wg2_b, lo, hi);
        float* fnext = (lvl < 2) ? (feat + (lvl+1)*B*C) : nullptr;
        dw_kernel<<<dim3(L/DTL, NROW), 256>>>(ain[lvl], lo, hi, aout[lvl], dets[lvl], fnext);
    }

    ortho_kernel<<<1, 32>>>(lo_all + 2*B*FL, scal);

    // i = 2: gates (no attn2) + fused attn1 for level 1 -> attn
    gatesf_kernel<false,true><<<dim3(L/128, B), 256, GSM_PLAIN>>>(
        a3, yh2, wt2 + 2*24*2048, gates_b + 2*C,
        nullptr, nullptr, nullptr, nullptr, a1,
        attn1_w + 1*(C/4)*C, attn1_b + (C/4), attn);
    // i = 1: gates + attn2(level 1) + fused attn1 for level 0 -> attn
    gatesf_kernel<true,true><<<dim3(L/128, B), 256, GSM_ATTN>>>(
        a1, yh1, wt2 + 1*24*2048, gates_b + 1*C,
        attn, w2t + 32*C, attn2_b + C, yh1, a2,
        attn1_w, attn1_b, attn);
    // i = 0: gates + attn2(level 0) -> yl
    gatesf_kernel<true,false><<<dim3(L/128, B), 256, GSM_ATTN>>>(
        a2, yh0, wt2, gates_b,
        attn, w2t, attn2_b, yh0, yl,
        nullptr, nullptr, nullptr);
}

// round 16
// speedup vs baseline: 2.3761x; 1.0743x over previous
#include <cuda_runtime.h>
#include <cuda_fp16.h>
#include <math.h>
#include <stdint.h>

#define B 32
#define C 128
#define L 4096
#define NROW (B*C)
#define BCL (B*C*L)            // 16777216
#define FL 9
#define DIM 512
#define NYL ((size_t)BCL)

// ---------------- scratch (device globals; no allocation) ----------------
__device__ float g_a1[BCL];
__device__ float g_a2[BCL];
__device__ float g_a3[BCL];
__device__ float g_attn[B*(C/4)*L];
__device__ float g_feat[3*B*C];          // per-level feature means
__device__ float g_h1[B*DIM];
__device__ float g_h2[B*2*DIM];
__device__ __align__(16) uint32_t g_wt2h[3*24*1024]; // fp16 gates weights [lvl][ch][co][8]
__device__ float g_w2t[2*32*C];          // attn2 weights [lvl][ci][co]

__device__ __forceinline__ float gelu_f(float x){
    return 0.5f*x*(1.0f+erff(x*0.7071067811865476f));
}
__device__ __forceinline__ float sigmoid_f(float x){
    return 1.0f/(1.0f+expf(-x));
}

// ---- packed f32x2 helpers (Blackwell FFMA2) ----
__device__ __forceinline__ unsigned long long pack2(float lo, float hi){
    unsigned long long r;
    asm("mov.b64 %0, {%1, %2};" : "=l"(r) : "f"(lo), "f"(hi));
    return r;
}
__device__ __forceinline__ unsigned long long fma2(unsigned long long a, unsigned long long b, unsigned long long c){
    unsigned long long d;
    asm("fma.rn.f32x2 %0, %1, %2, %3;" : "=l"(d) : "l"(a), "l"(b), "l"(c));
    return d;
}
__device__ __forceinline__ float2 unpack2(unsigned long long v){
    float2 f;
    asm("mov.b64 {%0, %1}, %2;" : "=f"(f.x), "=f"(f.y) : "l"(v));
    return f;
}

// ---- cp.async + mma helpers (baseline PTX) ----
__device__ __forceinline__ uint32_t smem_u32(const void* p){
    uint32_t a;
    asm("{ .reg .u64 t; cvta.to.shared.u64 t, %1; cvt.u32.u64 %0, t; }" : "=r"(a) : "l"(p));
    return a;
}
__device__ __forceinline__ void cp16(uint32_t dst, const void* src){
    asm volatile("cp.async.ca.shared.global [%0], [%1], 16;" :: "r"(dst), "l"(src) : "memory");
}
__device__ __forceinline__ void cp_commit(){
    asm volatile("cp.async.commit_group;" ::: "memory");
}
template<int N>
__device__ __forceinline__ void cp_wait(){
    asm volatile("cp.async.wait_group %0;" :: "n"(N) : "memory");
}
__device__ __forceinline__ void mma_f16(float* d, uint32_t a0, uint32_t a1, uint32_t a2, uint32_t a3,
                                        uint32_t b0, uint32_t b1){
    asm volatile("mma.sync.aligned.m16n8k16.row.col.f32.f16.f16.f32 "
        "{%0,%1,%2,%3}, {%4,%5,%6,%7}, {%8,%9}, {%0,%1,%2,%3};"
        : "+f"(d[0]), "+f"(d[1]), "+f"(d[2]), "+f"(d[3])
        : "r"(a0), "r"(a1), "r"(a2), "r"(a3), "r"(b0), "r"(b1));
}

// ---------------- mean over L (level 0 only) ----------------
__global__ __launch_bounds__(256) void mean_kernel(const float* __restrict__ x,
                                                   float* __restrict__ feat){
    int row = blockIdx.x;
    const float4* p = (const float4*)(x + (size_t)row*L);
    float s = 0.f;
    for (int i = threadIdx.x; i < L/4; i += 256){
        float4 v = p[i];
        s += (v.x+v.y)+(v.z+v.w);
    }
    __shared__ float red[256];
    red[threadIdx.x] = s; __syncthreads();
    for (int off = 128; off > 0; off >>= 1){
        if (threadIdx.x < off) red[threadIdx.x] += red[threadIdx.x+off];
        __syncthreads();
    }
    if (threadIdx.x == 0) feat[row] = red[0] * (1.0f/(float)L);
}

// ---------------- MLP layers (warp-per-output GEMV) ----------------
__global__ __launch_bounds__(256) void mlp_l1(const float* __restrict__ feat,
                                              const float* __restrict__ sw, const float* __restrict__ sb,
                                              float* __restrict__ h1){
    int b = blockIdx.y;
    int j = blockIdx.x*8 + (threadIdx.x >> 5);
    int lane = threadIdx.x & 31;
    float4 w = ((const float4*)(sw + (size_t)j*C))[lane];
    float4 f = ((const float4*)(feat + b*C))[lane];
    float s = w.x*f.x + w.y*f.y + w.z*f.z + w.w*f.w;
    #pragma unroll
    for (int off = 16; off > 0; off >>= 1) s += __shfl_xor_sync(0xffffffffu, s, off);
    if (lane == 0) h1[b*DIM + j] = gelu_f(s + sb[j]);
}

__global__ __launch_bounds__(256) void mlp_l2(const float* __restrict__ h1,
                                              const float* __restrict__ w1, const float* __restrict__ b1,
                                              float* __restrict__ h2){
    __shared__ __align__(16) float sh[DIM];
    int b = blockIdx.y, t = threadIdx.x;
    for (int i = t; i < DIM/4; i += 256)
        ((float4*)sh)[i] = ((const float4*)(h1 + b*DIM))[i];
    __syncthreads();
    int j = blockIdx.x*8 + (t >> 5);
    int lane = t & 31;
    const float4* wr = (const float4*)(w1 + (size_t)j*DIM);
    float s = 0.f;
    #pragma unroll
    for (int i = 0; i < 4; i++){
        float4 w = wr[i*32 + lane];
        float4 f = ((const float4*)sh)[i*32 + lane];
        s += w.x*f.x + w.y*f.y + w.z*f.z + w.w*f.w;
    }
    #pragma unroll
    for (int off = 16; off > 0; off >>= 1) s += __shfl_xor_sync(0xffffffffu, s, off);
    if (lane == 0) h2[b*2*DIM + j] = gelu_f(s + b1[j]);
}

__global__ __launch_bounds__(576) void mlp_l3(const float* __restrict__ h2,
                                              const float* __restrict__ w2, const float* __restrict__ b2,
                                              float* __restrict__ lo, float* __restrict__ hi){
    __shared__ __align__(16) float sh[2*DIM];
    int b = blockIdx.x, t = threadIdx.x;
    for (int i = t; i < 2*DIM/4; i += 576)
        ((float4*)sh)[i] = ((const float4*)(h2 + b*2*DIM))[i];
    __syncthreads();
    int j = t >> 5, lane = t & 31;     // 18 warps
    const float4* wr = (const float4*)(w2 + (size_t)j*2*DIM);
    float s = 0.f;
    #pragma unroll
    for (int i = 0; i < 8; i++){
        float4 w = wr[i*32 + lane];
        float4 f = ((const float4*)sh)[i*32 + lane];
        s += w.x*f.x + w.y*f.y + w.z*f.z + w.w*f.w;
    }
    #pragma unroll
    for (int off = 16; off > 0; off >>= 1) s += __shfl_xor_sync(0xffffffffu, s, off);
    if (lane == 0){
        float v = s + b2[j];
        if (j < FL) lo[b*FL + j] = v;
        else        hi[b*FL + (j-FL)] = v;
    }
}

// ---------------- ortho loss (last level only) + energy=0 ----------------
__global__ void ortho_kernel(const float* __restrict__ lo, float* __restrict__ out_scalars){
    int b = threadIdx.x;
    float v[FL]; float ss = 0.f;
    #pragma unroll
    for (int k = 0; k < FL; k++){ v[k] = lo[b*FL+k]; ss += v[k]*v[k]; }
    float den = sqrtf(ss) + 1e-8f;
    float S = 0.f, sq = 0.f;
    #pragma unroll
    for (int k = 0; k < FL; k++){
        float n = v[k]/den;
        S  += fabsf(n);
        sq += n*n;
    }
    float S2  = S*S;
    float amp = fabsf(sq - 1.0f);
    float sm  = fabsf(v[0]);
    #pragma unroll
    for (int k = 1; k < FL; k++) sm += fabsf(v[k]-v[k-1]);
    sm += fabsf(v[FL-1]);
    #pragma unroll
    for (int off = 16; off > 0; off >>= 1){
        S2  += __shfl_xor_sync(0xffffffffu, S2,  off);
        amp += __shfl_xor_sync(0xffffffffu, amp, off);
        sm  += __shfl_xor_sync(0xffffffffu, sm,  off);
    }
    if (b == 0){
        float shift  = 3.0f * S2 / (32.0f*81.0f);
        float ampm   = amp / 32.0f;
        float smm    = sm / (32.0f*10.0f);
        out_scalars[0] = 0.01f*(shift + ampm) + 0.1f*smm;
        out_scalars[1] = 0.0f;
    }
}

// ---------------- per-sample depthwise 9-tap (edge pad) + mean accumulate ----------------
#define DTL 1024
__global__ __launch_bounds__(256) void dw_kernel(
    const float* __restrict__ x, const float* __restrict__ lo, const float* __restrict__ hi,
    float* __restrict__ out_a, float* __restrict__ out_d, float* __restrict__ feat_next)
{
    int row = blockIdx.y;
    int b   = row >> 7;
    int l0  = blockIdx.x * DTL;
    __shared__ __align__(16) float s[DTL + 16];
    __shared__ float wsum[8];
    const float* xr = x + (size_t)row * L;
    int t = threadIdx.x, lane = t & 31, wid = t >> 5;
    {
        const float4* xv = (const float4*)(xr + l0);
        ((float4*)(s + 4))[t] = xv[t];
    }
    if (t < 4){
        int li = l0 - 4 + t;
        s[t] = xr[max(li, 0)];
        int ri = l0 + DTL + t;
        s[DTL + 4 + t] = xr[min(ri, L-1)];
    }
    unsigned long long pf[FL];
    #pragma unroll
    for (int k = 0; k < FL; k++) pf[k] = pack2(__ldg(&lo[b*FL+k]), __ldg(&hi[b*FL+k]));
    __syncthreads();

    int i0 = t * 4;
    float win[12];
    #pragma unroll
    for (int j = 0; j < 12; j++) win[j] = s[i0 + j];
    unsigned long long acc[4];
    #pragma unroll
    for (int p = 0; p < 4; p++) acc[p] = 0ull;
    #pragma unroll
    for (int k = 0; k < FL; k++){
        #pragma unroll
        for (int p = 0; p < 4; p++){
            unsigned long long vv = pack2(win[p+k], win[p+k]);
            acc[p] = fma2(vv, pf[k], acc[p]);
        }
    }
    float4 ra, rd;
    float2 f0 = unpack2(acc[0]), f1 = unpack2(acc[1]), f2 = unpack2(acc[2]), f3 = unpack2(acc[3]);
    ra.x = f0.x; ra.y = f1.x; ra.z = f2.x; ra.w = f3.x;
    rd.x = f0.y; rd.y = f1.y; rd.z = f2.y; rd.w = f3.y;
    size_t idx = (size_t)row*L + l0 + i0;
    *(float4*)(out_a + idx) = ra;
    *(float4*)(out_d + idx) = rd;

    if (feat_next){
        float s4 = (ra.x + ra.y) + (ra.z + ra.w);
        #pragma unroll
        for (int off = 16; off > 0; off >>= 1) s4 += __shfl_xor_sync(0xffffffffu, s4, off);
        if (lane == 0) wsum[wid] = s4;
        __syncthreads();
        if (t == 0){
            float tot = 0.f;
            #pragma unroll
            for (int w = 0; w < 8; w++) tot += wsum[w];
            atomicAdd(feat_next + row, tot * (1.0f/(float)L));
        }
    }
}

// ---------------- weight prep: fp16 fragment-ordered chunks ----------------
// wt2h[lvl][ch=tap*8+ch8][co][p], p = c4*2 + w: u32 = half2( W[ci], W[ci+1] ),
// ci = ch8*16 + 2*c4 + (w ? 8 : 0)
__global__ void wprep_f16(const float* __restrict__ gw, uint32_t* __restrict__ wt2h){
    int idx = blockIdx.x*256 + threadIdx.x;
    if (idx < 3*24*1024){
        int lvl = idx / (24*1024);
        int r   = idx % (24*1024);
        int ch  = r / 1024;
        int q   = r % 1024;
        int co  = q >> 3;
        int p   = q & 7;
        int c4 = p >> 1, w = p & 1;
        int tap = ch >> 3;
        int ci  = (ch & 7)*16 + 2*c4 + (w ? 8 : 0);
        float f0 = gw[(((size_t)lvl*C + co)*C + ci)*3 + tap];
        float f1 = gw[(((size_t)lvl*C + co)*C + ci + 1)*3 + tap];
        __half2 h2 = __floats2half2_rn(f0, f1);
        wt2h[idx] = *(const uint32_t*)&h2;
    }
}
__global__ void prep2_kernel(const float* __restrict__ attn2_w, float* __restrict__ w2t,
                             float* __restrict__ feat){
    int idx = blockIdx.x*256 + threadIdx.x;
    if (idx < 2*32*C){
        int lvl = idx / (32*C);
        int r   = idx % (32*C);
        int ci  = r >> 7, co = r & 127;
        w2t[idx] = attn2_w[((size_t)lvl*C + co)*32 + ci];
    }
    if (idx < 2*B*C) feat[B*C + idx] = 0.f;   // zero feat levels 1,2
}

// ---------------- fused gates: fp16 mma conv3 + attn2 (phase1) + attn1 (phase3) ----
// s_xh[r][ci] fp16, r = l - l0 + 1 (r in [0,130)), pitch PH=136 halves (PHW=68 words)
#define PH  136
#define PHW 68
#define SO_WB 35360                     // 130*136*2
#define WCH_B 4096                      // one chunk: [co128][8] u32
#define SO_W2 (SO_WB + 16384)           // 51744 (ring 12KB + s_w1 16KB region)
#define GSM_ATTN  (SO_W2 + 32*C*4)      // 68128
#define GSM_PLAIN SO_W2                 // 51744

template<bool ATTN, bool A1>
__global__ __launch_bounds__(256, 2) void gatesf_kernel(
    const float* __restrict__ cur, const float* __restrict__ det_raw,
    const uint32_t* __restrict__ wt2h, const float* __restrict__ bias,
    const float* __restrict__ a_in, const float* __restrict__ w2t, const float* __restrict__ bias2,
    float* __restrict__ yh_out, float* __restrict__ out,
    const float* __restrict__ w1, const float* __restrict__ b1, float* __restrict__ a_out)
{
    extern __shared__ __align__(16) char smem[];
    __half* s_xh = (__half*)smem;            // [130][PH]
    float*  s_w2 = (float*)(smem + SO_W2);   // phase1 weights
    uint32_t wb_base = smem_u32(smem + SO_WB);
    int l0 = blockIdx.x*128, b = blockIdx.y, t = threadIdx.x;
    int wid = t >> 5, lane = t & 31;
    int g = lane >> 2, c4 = lane & 3;
    int co_w = (wid & 3)*32;            // warp co base (m)
    int n0   = (wid >> 2)*64;           // warp l base (n)

    // prologue prefetch chunks 0,1 (4KB each, 16B/thread)
    {
        const char* src = (const char*)wt2h;
        cp16(wb_base + t*16, src + t*16);
        cp_commit();
        cp16(wb_base + WCH_B + t*16, src + WCH_B + t*16);
        cp_commit();
    }

    // ---- fill s_xh transposed fp16: rows r=1..128 interior, edges r=0/129 ----
    #pragma unroll 4
    for (int k = 0; k < 16; k++){
        int idx4 = t + k*256;
        int ci = idx4 >> 5, j4 = (idx4 & 31)*4;
        float4 v = *(const float4*)(cur + ((size_t)(b*C+ci))*L + l0 + j4);
        s_xh[(j4+1)*PH + ci] = __float2half(v.x);
        s_xh[(j4+2)*PH + ci] = __float2half(v.y);
        s_xh[(j4+3)*PH + ci] = __float2half(v.z);
        s_xh[(j4+4)*PH + ci] = __float2half(v.w);
    }
    {
        int ci = t & 127;
        size_t row = (size_t)(b*C+ci)*L;
        if (t < 128){
            float v = (l0 > 0) ? cur[row + l0 - 1] : 0.f;
            s_xh[ci] = __float2half(v);                    // r = 0
        } else {
            float v = (l0 + 128 < L) ? cur[row + l0 + 128] : 0.f;
            s_xh[129*PH + ci] = __float2half(v);           // r = 129
        }
    }
    if (ATTN){
        for (int idx = t; idx < 32*C; idx += 256) s_w2[idx] = w2t[idx];
    }
    __syncthreads();

    // ---- phase 1 (ATTN): det' = det*(1+sig(W2*a+b2)) -> yh_out, 2 half-passes ----
    if (ATTN){
        int co0 = wid*16, lq = lane*4;
        #pragma unroll 1
        for (int half = 0; half < 2; half++){
            unsigned long long acc2[4][4];
            #pragma unroll
            for (int c = 0; c < 4; c++)
                #pragma unroll
                for (int q = 0; q < 4; q++) acc2[c][q] = 0ull;
            #pragma unroll 4
            for (int ci = 0; ci < 32; ci++){
                float4 xv = *(const float4*)(a_in + ((size_t)(b*32+ci))*L + l0 + lq);
                unsigned long long p0 = pack2(xv.x, xv.x);
                unsigned long long p1 = pack2(xv.y, xv.y);
                unsigned long long p2 = pack2(xv.z, xv.z);
                unsigned long long p3 = pack2(xv.w, xv.w);
                const ulonglong2* wp = (const ulonglong2*)(&s_w2[ci*C + co0 + half*8]);
                unsigned long long wr[4];
                ((ulonglong2*)wr)[0] = wp[0];
                ((ulonglong2*)wr)[1] = wp[1];
                #pragma unroll
                for (int c = 0; c < 4; c++){
                    acc2[c][0] = fma2(wr[c], p0, acc2[c][0]);
                    acc2[c][1] = fma2(wr[c], p1, acc2[c][1]);
                    acc2[c][2] = fma2(wr[c], p2, acc2[c][2]);
                    acc2[c][3] = fma2(wr[c], p3, acc2[c][3]);
                }
            }
            #pragma unroll
            for (int c = 0; c < 4; c++){
                int co = co0 + half*8 + 2*c;
                float2 z[4];
                #pragma unroll
                for (int q = 0; q < 4; q++) z[q] = unpack2(acc2[c][q]);
                #pragma unroll
                for (int s = 0; s < 2; s++){
                    float bv = __ldg(&bias2[co+s]);
                    size_t idx = ((size_t)(b*C+co+s))*L + l0 + lq;
                    float4 dv = *(const float4*)(det_raw + idx);
                    dv.x *= 1.0f + sigmoid_f((s ? z[0].y : z[0].x) + bv);
                    dv.y *= 1.0f + sigmoid_f((s ? z[1].y : z[1].x) + bv);
                    dv.z *= 1.0f + sigmoid_f((s ? z[2].y : z[2].x) + bv);
                    dv.w *= 1.0f + sigmoid_f((s ? z[3].y : z[3].x) + bv);
                    *(float4*)(yh_out + idx) = dv;
                }
            }
        }
    }

    // ---- phase 2: fp16 mma mainloop (24 chunks: tap = ch>>3, ci16 = (ch&7)*16) ----
    float d[2][8][4];
    #pragma unroll
    for (int mi = 0; mi < 2; mi++)
        #pragma unroll
        for (int ni = 0; ni < 8; ni++)
            #pragma unroll
            for (int r = 0; r < 4; r++) d[mi][ni][r] = 0.f;

    const uint32_t* sxh_u = (const uint32_t*)smem;
    for (int ch = 0; ch < 24; ch++){
        if (ch < 22) cp_wait<1>(); else cp_wait<0>();
        __syncthreads();
        if (ch + 2 < 24){
            uint32_t dst = wb_base + ((ch+2)%3)*WCH_B;
            const char* src = (const char*)wt2h + (size_t)(ch+2)*WCH_B;
            cp16(dst + t*16, src + t*16);
            cp_commit();
        }
        int tap = ch >> 3;
        int cw0 = (ch & 7)*8;     // ci_base/2 (word offset)
        const uint32_t* wch = (const uint32_t*)(smem + SO_WB + (ch%3)*WCH_B);
        // A frags: LDS.64 gives (a0,a2) at co, (a1,a3) at co+8
        uint32_t af[2][4];
        #pragma unroll
        for (int mi = 0; mi < 2; mi++){
            int co = co_w + mi*16 + g;
            unsigned long long w0 = *(const unsigned long long*)(wch + co*8     + c4*2);
            unsigned long long w8 = *(const unsigned long long*)(wch + (co+8)*8 + c4*2);
            af[mi][0] = (uint32_t)w0;
            af[mi][2] = (uint32_t)(w0 >> 32);
            af[mi][1] = (uint32_t)w8;
            af[mi][3] = (uint32_t)(w8 >> 32);
        }
        int r0 = n0 + g + tap;
        const uint32_t* xb = sxh_u + r0*PHW + cw0 + c4;
        #pragma unroll
        for (int ni = 0; ni < 8; ni++){
            uint32_t b0v = xb[ni*8*PHW];
            uint32_t b1v = xb[ni*8*PHW + 4];
            mma_f16(d[0][ni], af[0][0], af[0][1], af[0][2], af[0][3], b0v, b1v);
            mma_f16(d[1][ni], af[1][0], af[1][1], af[1][2], af[1][3], b0v, b1v);
        }
    }
    __syncthreads();     // all B reads done before A1 restage overwrites s_xh

    // ---- epilogue: out = cur(global) + sig(z+bias)*det'  (direct from frags) ----
    {
        const float* dsrc = ATTN ? yh_out : det_raw;
        #pragma unroll
        for (int mi = 0; mi < 2; mi++){
            #pragma unroll
            for (int half = 0; half < 2; half++){
                int co = co_w + mi*16 + g + half*8;
                float bv = __ldg(&bias[co]);
                size_t rowg = ((size_t)(b*C+co))*L + l0;
                #pragma unroll
                for (int ni = 0; ni < 8; ni++){
                    int l = n0 + ni*8 + c4*2;
                    float z0 = d[mi][ni][half*2 + 0];
                    float z1 = d[mi][ni][half*2 + 1];
                    float2 cv = *(const float2*)(cur + rowg + l);
                    float2 dv = *(const float2*)(dsrc + rowg + l);
                    float o0 = cv.x + sigmoid_f(z0 + bv)*dv.x;
                    float o1 = cv.y + sigmoid_f(z1 + bv)*dv.y;
                    *(float2*)(out + rowg + l) = make_float2(o0, o1);
                    if (A1){
                        s_xh[(l+1)*PH + co] = __float2half(o0);
                        s_xh[(l+2)*PH + co] = __float2half(o1);
                    }
                }
            }
        }
    }

    // ---- phase 3 (A1): a_out = gelu(W1*out + b1), out read from s_xh (fp16) ----
    if (A1){
        __syncthreads();
        float* s_w1 = (float*)(smem + SO_WB);   // 16KB region, ring drained
        for (int idx = t; idx < 32*C; idx += 256){
            int ci = idx >> 5, c2 = idx & 31;
            s_w1[idx] = w1[c2*C + ci];
        }
        __syncthreads();
        int c2b = wid*4;
        unsigned long long acc3[2][4];
        #pragma unroll
        for (int pc = 0; pc < 2; pc++)
            #pragma unroll
            for (int q = 0; q < 4; q++) acc3[pc][q] = 0ull;
        #pragma unroll 2
        for (int ci2 = 0; ci2 < 64; ci2++){
            ulonglong2 wvA = *(const ulonglong2*)(&s_w1[(2*ci2)*32 + c2b]);
            ulonglong2 wvB = *(const ulonglong2*)(&s_w1[(2*ci2+1)*32 + c2b]);
            #pragma unroll
            for (int q = 0; q < 4; q++){
                uint32_t xv = sxh_u[(lane + 32*q + 1)*PHW + ci2];
                float2 xf = __half22float2(*(const __half2*)&xv);
                unsigned long long p0 = pack2(xf.x, xf.x);
                unsigned long long p1 = pack2(xf.y, xf.y);
                acc3[0][q] = fma2(wvA.x, p0, acc3[0][q]);
                acc3[0][q] = fma2(wvB.x, p1, acc3[0][q]);
                acc3[1][q] = fma2(wvA.y, p0, acc3[1][q]);
                acc3[1][q] = fma2(wvB.y, p1, acc3[1][q]);
            }
        }
        #pragma unroll
        for (int pc = 0; pc < 2; pc++){
            int c2 = c2b + 2*pc;
            float b10 = __ldg(&b1[c2]);
            float b11 = __ldg(&b1[c2+1]);
            #pragma unroll
            for (int q = 0; q < 4; q++){
                float2 z = unpack2(acc3[pc][q]);
                size_t ix = ((size_t)(b*32 + c2))*L + l0 + lane + 32*q;
                a_out[ix]     = gelu_f(z.x + b10);
                a_out[ix + L] = gelu_f(z.y + b11);
            }
        }
    }
}

// ---------------- host launch ----------------
extern "C" void kernel_launch(void* const* d_in, const int* in_sizes, int n_in,
                              void* d_out, int out_size)
{
    const float* x       = (const float*)d_in[0];
    const float* stat_w  = (const float*)d_in[1];
    const float* stat_b  = (const float*)d_in[2];
    const float* wg1_w   = (const float*)d_in[3];
    const float* wg1_b   = (const float*)d_in[4];
    const float* wg2_w   = (const float*)d_in[5];
    const float* wg2_b   = (const float*)d_in[6];
    const float* gates_w = (const float*)d_in[7];
    const float* gates_b = (const float*)d_in[8];
    const float* attn1_w = (const float*)d_in[9];
    const float* attn1_b = (const float*)d_in[10];
    const float* attn2_w = (const float*)d_in[11];
    const float* attn2_b = (const float*)d_in[12];
    float* out = (float*)d_out;

    float *a1, *a2, *a3, *attn, *feat, *h1, *h2, *w2t;
    uint32_t *wt2h;
    cudaGetSymbolAddress((void**)&a1,   g_a1);
    cudaGetSymbolAddress((void**)&a2,   g_a2);
    cudaGetSymbolAddress((void**)&a3,   g_a3);
    cudaGetSymbolAddress((void**)&attn, g_attn);
    cudaGetSymbolAddress((void**)&feat, g_feat);
    cudaGetSymbolAddress((void**)&h1,   g_h1);
    cudaGetSymbolAddress((void**)&h2,   g_h2);
    cudaGetSymbolAddress((void**)&wt2h, g_wt2h);
    cudaGetSymbolAddress((void**)&w2t,  g_w2t);

    float* yl  = out;
    float* yh0 = out + NYL;
    float* yh1 = out + 2*NYL;
    float* yh2 = out + 3*NYL;
    float* scal= out + 4*NYL;
    float* lo_all = out + 4*NYL + 2;
    float* hi_all = lo_all + 3*B*FL;

    cudaFuncSetAttribute((const void*)gatesf_kernel<false,true>,  cudaFuncAttributeMaxDynamicSharedMemorySize, GSM_PLAIN);
    cudaFuncSetAttribute((const void*)gatesf_kernel<true,true>,   cudaFuncAttributeMaxDynamicSharedMemorySize, GSM_ATTN);
    cudaFuncSetAttribute((const void*)gatesf_kernel<true,false>,  cudaFuncAttributeMaxDynamicSharedMemorySize, GSM_ATTN);

    wprep_f16<<<(3*24*1024 + 255)/256, 256>>>(gates_w, wt2h);
    prep2_kernel<<<(2*32*C + 255)/256, 256>>>(attn2_w, w2t, feat);

    const float* ain[3]  = {x, a1, a2};
    float*       aout[3] = {a1, a2, a3};
    float*       dets[3] = {yh0, yh1, yh2};

    mean_kernel<<<NROW, 256>>>(x, feat);
    for (int lvl = 0; lvl < 3; lvl++){
        float* lo = lo_all + lvl*B*FL;
        float* hi = hi_all + lvl*B*FL;
        const float* f = feat + lvl*B*C;
        mlp_l1<<<dim3(DIM/8, B), 256>>>(f, stat_w, stat_b, h1);
        mlp_l2<<<dim3(2*DIM/8, B), 256>>>(h1, wg1_w, wg1_b, h2);
        mlp_l3<<<B, 576>>>(h2, wg2_w, wg2_b, lo, hi);
        float* fnext = (lvl < 2) ? (feat + (lvl+1)*B*C) : nullptr;
        dw_kernel<<<dim3(L/DTL, NROW), 256>>>(ain[lvl], lo, hi, aout[lvl], dets[lvl], fnext);
    }

    ortho_kernel<<<1, 32>>>(lo_all + 2*B*FL, scal);

    // i = 2: gates (no attn2) + fused attn1 for level 1 -> attn
    gatesf_kernel<false,true><<<dim3(L/128, B), 256, GSM_PLAIN>>>(
        a3, yh2, wt2h + 2*24*1024, gates_b + 2*C,
        nullptr, nullptr, nullptr, nullptr, a1,
        attn1_w + 1*(C/4)*C, attn1_b + (C/4), attn);
    // i = 1: gates + attn2(level 1) + fused attn1 for level 0 -> attn
    gatesf_kernel<true,true><<<dim3(L/128, B), 256, GSM_ATTN>>>(
        a1, yh1, wt2h + 1*24*1024, gates_b + 1*C,
        attn, w2t + 32*C, attn2_b + C, yh1, a2,
        attn1_w, attn1_b, attn);
    // i = 0: gates + attn2(level 0) -> yl
    gatesf_kernel<true,false><<<dim3(L/128, B), 256, GSM_ATTN>>>(
        a2, yh0, wt2h, gates_b,
        attn, w2t, attn2_b, yh0, yl,
        nullptr, nullptr, nullptr);
}